// round 1
// baseline (speedup 1.0000x reference)
#include <cuda_runtime.h>
#include <math.h>

// Problem constants
#define Bsz   8
#define Esz   256
#define Nsz   32
#define Dsz   512
#define RDsz  768
#define Rsz   2000
#define Lsz   2
#define Ksel  8
#define Msz   32
#define Hsz   8
#define DHsz  64
#define HLLMsz 4096
#define BE    (Bsz*Esz)   // 2048

// Scratch (static device globals; no allocation at runtime)
__device__ float g_ptable[Rsz*Dsz];     // projected relation table [2000,512]
__device__ float g_norms[Rsz];
__device__ float g_agg[BE*Dsz];
__device__ float g_states[BE*Dsz];
__device__ float g_tmp[BE*Dsz];
__device__ float g_tmp2[BE*Dsz];
__device__ float g_hid[BE*4*Dsz];       // FF hidden [2048,2048]
__device__ float g_q[Msz*Dsz];
__device__ float g_k[BE*Dsz];
__device__ float g_v[BE*Dsz];
__device__ float g_mem[Bsz*Msz*Dsz];
__device__ float g_mem2[Bsz*Msz*Dsz];

// ---------------------------------------------------------------------------
// Generic fp32 GEMM: C[M,N] = A[M,K] @ W[N,K]^T + bias[N]  (optional exact GELU)
// BM=64, BN=128, BK=16, 128 threads, 8x8 microtile per thread.
// ---------------------------------------------------------------------------
template<bool GELU>
__global__ __launch_bounds__(128)
void gemm_nt(const float* __restrict__ A, const float* __restrict__ W,
             const float* __restrict__ bias, float* __restrict__ C,
             int Mm, int Nn, int Kk)
{
    __shared__ float As[16][64];
    __shared__ float Bs[16][128];
    const int m0 = blockIdx.y * 64;
    const int n0 = blockIdx.x * 128;
    const int tid = threadIdx.x;
    const int tr = tid >> 4;     // 0..7
    const int tc = tid & 15;     // 0..15

    float acc[8][8];
#pragma unroll
    for (int i = 0; i < 8; i++)
#pragma unroll
        for (int j = 0; j < 8; j++) acc[i][j] = 0.f;

    const int arow = tid >> 1;          // 0..63
    const int akk  = (tid & 1) * 8;     // 0 or 8
    const int brow = tid;               // 0..127

    for (int k0 = 0; k0 < Kk; k0 += 16) {
        // A tile: 64 rows x 16 k (transposed into As[k][m])
        {
            float4 a0 = make_float4(0,0,0,0), a1 = make_float4(0,0,0,0);
            if (m0 + arow < Mm) {
                const float* ap = A + (size_t)(m0 + arow) * Kk + k0 + akk;
                a0 = *(const float4*)(ap);
                a1 = *(const float4*)(ap + 4);
            }
            As[akk+0][arow] = a0.x; As[akk+1][arow] = a0.y;
            As[akk+2][arow] = a0.z; As[akk+3][arow] = a0.w;
            As[akk+4][arow] = a1.x; As[akk+5][arow] = a1.y;
            As[akk+6][arow] = a1.z; As[akk+7][arow] = a1.w;
        }
        // B tile: 128 rows (N) x 16 k (transposed into Bs[k][n])
        {
            float4 b0 = make_float4(0,0,0,0), b1 = make_float4(0,0,0,0);
            float4 b2 = make_float4(0,0,0,0), b3 = make_float4(0,0,0,0);
            if (n0 + brow < Nn) {
                const float* bp = W + (size_t)(n0 + brow) * Kk + k0;
                b0 = *(const float4*)(bp);
                b1 = *(const float4*)(bp + 4);
                b2 = *(const float4*)(bp + 8);
                b3 = *(const float4*)(bp + 12);
            }
            Bs[0][brow]  = b0.x; Bs[1][brow]  = b0.y; Bs[2][brow]  = b0.z; Bs[3][brow]  = b0.w;
            Bs[4][brow]  = b1.x; Bs[5][brow]  = b1.y; Bs[6][brow]  = b1.z; Bs[7][brow]  = b1.w;
            Bs[8][brow]  = b2.x; Bs[9][brow]  = b2.y; Bs[10][brow] = b2.z; Bs[11][brow] = b2.w;
            Bs[12][brow] = b3.x; Bs[13][brow] = b3.y; Bs[14][brow] = b3.z; Bs[15][brow] = b3.w;
        }
        __syncthreads();
#pragma unroll
        for (int k = 0; k < 16; k++) {
            float ra[8], rb[8];
            *(float4*)&ra[0] = *(const float4*)&As[k][tr*8];
            *(float4*)&ra[4] = *(const float4*)&As[k][tr*8 + 4];
            *(float4*)&rb[0] = *(const float4*)&Bs[k][tc*8];
            *(float4*)&rb[4] = *(const float4*)&Bs[k][tc*8 + 4];
#pragma unroll
            for (int i = 0; i < 8; i++)
#pragma unroll
                for (int j = 0; j < 8; j++)
                    acc[i][j] = fmaf(ra[i], rb[j], acc[i][j]);
        }
        __syncthreads();
    }
#pragma unroll
    for (int i = 0; i < 8; i++) {
        int row = m0 + tr*8 + i;
        if (row >= Mm) break;       // thread rows are contiguous: break is safe
        float* cp = C + (size_t)row * Nn + n0 + tc*8;
#pragma unroll
        for (int j = 0; j < 8; j++) {
            float vv = acc[i][j] + bias[n0 + tc*8 + j];
            if (GELU) vv = 0.5f * vv * (1.f + erff(vv * 0.70710678118654752f));
            cp[j] = vv;
        }
    }
}

// ---------------------------------------------------------------------------
__device__ __forceinline__ float block_sum_256(float v, float* red)
{
    for (int o = 16; o; o >>= 1) v += __shfl_xor_sync(0xffffffffu, v, o);
    int w = threadIdx.x >> 5;
    if ((threadIdx.x & 31) == 0) red[w] = v;
    __syncthreads();
    float r = 0.f;
    if (threadIdx.x < 8) {
        r = red[threadIdx.x];
        for (int o = 4; o; o >>= 1) r += __shfl_xor_sync(0xffu, r, o);
        if (threadIdx.x == 0) red[0] = r;
    }
    __syncthreads();
    r = red[0];
    __syncthreads();
    return r;
}

// norms of projected relation table rows
__global__ __launch_bounds__(128)
void row_norm_kernel()
{
    int r = blockIdx.x;
    int tid = threadIdx.x;
    float s = 0.f;
#pragma unroll
    for (int d = tid; d < Dsz; d += 128) {
        float v = g_ptable[r*Dsz + d];
        s = fmaf(v, v, s);
    }
    for (int o = 16; o; o >>= 1) s += __shfl_xor_sync(0xffffffffu, s, o);
    __shared__ float red[4];
    if ((tid & 31) == 0) red[tid >> 5] = s;
    __syncthreads();
    if (tid == 0)
        g_norms[r] = sqrtf(red[0] + red[1] + red[2] + red[3]);
}

// per-edge: cosine sims to 32 neighbors, stable top-8, mean-aggregate; init states
__global__ __launch_bounds__(256)
void sim_topk_agg(const int* __restrict__ eids, const int* __restrict__ nids)
{
    int be = blockIdx.x;                 // 0..2047
    int tid = threadIdx.x;
    __shared__ float ev[Dsz];
    __shared__ float sims[Nsz];
    __shared__ int   selnid[Ksel];
    int eid = eids[be];
    for (int d = tid; d < Dsz; d += 256) ev[d] = g_ptable[eid*Dsz + d];
    __syncthreads();
    float enorm = fmaxf(g_norms[eid], 1e-12f);
    int warp = tid >> 5, lane = tid & 31;
#pragma unroll
    for (int t = 0; t < 4; t++) {
        int n = warp*4 + t;
        int nid = nids[be*Nsz + n];
        const float* nv = &g_ptable[nid*Dsz];
        float s = 0.f;
#pragma unroll 4
        for (int d = lane; d < Dsz; d += 32) s = fmaf(nv[d], ev[d], s);
        for (int o = 16; o; o >>= 1) s += __shfl_xor_sync(0xffffffffu, s, o);
        if (lane == 0)
            sims[n] = s / (enorm * fmaxf(g_norms[nid], 1e-12f));
    }
    __syncthreads();
    if (tid == 0) {
        unsigned used = 0;
        for (int j = 0; j < Ksel; j++) {
            float best = -3.402823466e38f; int bi = 0;
            for (int n = 0; n < Nsz; n++)
                if (!((used >> n) & 1u) && sims[n] > best) { best = sims[n]; bi = n; }
            used |= 1u << bi;
            selnid[j] = nids[be*Nsz + bi];
        }
    }
    __syncthreads();
    for (int d = tid; d < Dsz; d += 256) {
        float s = 0.f;
#pragma unroll
        for (int j = 0; j < Ksel; j++) s += g_ptable[(size_t)selnid[j]*Dsz + d];
        g_agg[(size_t)be*Dsz + d]    = s * 0.125f;
        g_states[(size_t)be*Dsz + d] = ev[d];       // states init = rel_vec
    }
}

// states = LN(states + add) * (optional mask)
__global__ __launch_bounds__(256)
void add_ln(const float* __restrict__ x, const float* __restrict__ add,
            float* __restrict__ out, const float* __restrict__ g,
            const float* __restrict__ b, const float* __restrict__ mask)
{
    int row = blockIdx.x;
    int tid = threadIdx.x;
    __shared__ float red[8];
    size_t base = (size_t)row * Dsz;
    float v0 = x[base + tid]       + add[base + tid];
    float v1 = x[base + tid + 256] + add[base + tid + 256];
    float total = block_sum_256(v0 + v1, red);
    float mu = total * (1.f / Dsz);
    float d0 = v0 - mu, d1 = v1 - mu;
    float var = block_sum_256(d0*d0 + d1*d1, red) * (1.f / Dsz);
    float inv = rsqrtf(var + 1e-5f);
    float mk = mask ? mask[row] : 1.f;
    out[base + tid]       = (d0 * inv * g[tid]       + b[tid])       * mk;
    out[base + tid + 256] = (d1 * inv * g[tid + 256] + b[tid + 256]) * mk;
}

// memory-token cross attention: block per (b,m)
__global__ __launch_bounds__(256)
void mem_attn(const float* __restrict__ mask)
{
    int b = blockIdx.x >> 5;
    int m = blockIdx.x & 31;
    int tid = threadIdx.x;
    __shared__ float qs[Dsz];
    __shared__ float sc[Hsz][Esz];
    qs[tid]       = g_q[m*Dsz + tid];
    qs[tid + 256] = g_q[m*Dsz + tid + 256];
    __syncthreads();
    {
        int e = tid;
        const float* kr = &g_k[((size_t)b*Esz + e)*Dsz];
        float mk = mask[b*Esz + e];
#pragma unroll
        for (int h = 0; h < Hsz; h++) {
            float s = 0.f;
#pragma unroll
            for (int d = 0; d < DHsz; d += 4) {
                float4 kq = *(const float4*)&kr[h*DHsz + d];
                float4 qq = *(const float4*)&qs[h*DHsz + d];
                s = fmaf(kq.x, qq.x, s); s = fmaf(kq.y, qq.y, s);
                s = fmaf(kq.z, qq.z, s); s = fmaf(kq.w, qq.w, s);
            }
            s *= 0.125f;   // 1/sqrt(64)
            sc[h][e] = (mk == 0.f) ? -3.402823466e38f : s;
        }
    }
    __syncthreads();
    // softmax: warp w handles head h=w over 256 edges
    {
        int w = tid >> 5, lane = tid & 31;
        float vals[8];
        float mx = -3.402823466e38f;
#pragma unroll
        for (int j = 0; j < 8; j++) { vals[j] = sc[w][lane + 32*j]; mx = fmaxf(mx, vals[j]); }
        for (int o = 16; o; o >>= 1) mx = fmaxf(mx, __shfl_xor_sync(0xffffffffu, mx, o));
        float sm = 0.f;
#pragma unroll
        for (int j = 0; j < 8; j++) { vals[j] = expf(vals[j] - mx); sm += vals[j]; }
        for (int o = 16; o; o >>= 1) sm += __shfl_xor_sync(0xffffffffu, sm, o);
        float inv = 1.f / sm;
#pragma unroll
        for (int j = 0; j < 8; j++) sc[w][lane + 32*j] = vals[j] * inv;
    }
    __syncthreads();
    float a0 = 0.f, a1 = 0.f;
    int od0 = tid, od1 = tid + 256;
    int h0 = od0 >> 6, h1 = od1 >> 6;
    for (int e = 0; e < Esz; e++) {
        const float* vr = &g_v[((size_t)b*Esz + e)*Dsz];
        a0 = fmaf(sc[h0][e], vr[od0], a0);
        a1 = fmaf(sc[h1][e], vr[od1], a1);
    }
    size_t ob = (size_t)blockIdx.x * Dsz;
    g_mem[ob + od0] = a0;
    g_mem[ob + od1] = a1;
}

// zero memory for batches with no edges
__global__ __launch_bounds__(256)
void zero_noedge(const float* __restrict__ mask)
{
    int b = blockIdx.x;
    __shared__ float red[8];
    float total = block_sum_256(mask[b*Esz + threadIdx.x], red);
    if (total == 0.f) {
        for (int i = threadIdx.x; i < Msz*Dsz; i += 256)
            g_mem2[(size_t)b*Msz*Dsz + i] = 0.f;
    }
}

// ---------------------------------------------------------------------------
static void launch_gemm(const float* A, const float* W, const float* bias,
                        float* C, int M, int N, int K, bool gelu)
{
    dim3 grid((N + 127) / 128, (M + 63) / 64);
    if (gelu) gemm_nt<true ><<<grid, 128>>>(A, W, bias, C, M, N, K);
    else      gemm_nt<false><<<grid, 128>>>(A, W, bias, C, M, N, K);
}

extern "C" void kernel_launch(void* const* d_in, const int* in_sizes, int n_in,
                              void* d_out, int out_size)
{
    (void)in_sizes; (void)n_in; (void)out_size;
    const int*   eids   = (const int*)d_in[0];
    const int*   nids   = (const int*)d_in[1];
    const float* mask   = (const float*)d_in[2];
    const float* rel_emb= (const float*)d_in[3];
    const float* rp_w   = (const float*)d_in[4];
    const float* rp_b   = (const float*)d_in[5];
    const float* vw     = (const float*)d_in[6];
    const float* vbp    = (const float*)d_in[7];
    const float* ow     = (const float*)d_in[8];
    const float* obp    = (const float*)d_in[9];
    const float* n1g    = (const float*)d_in[10];
    const float* n1b    = (const float*)d_in[11];
    const float* n2g    = (const float*)d_in[12];
    const float* n2b    = (const float*)d_in[13];
    const float* w1     = (const float*)d_in[14];
    const float* b1     = (const float*)d_in[15];
    const float* w2     = (const float*)d_in[16];
    const float* b2     = (const float*)d_in[17];
    const float* mem_q  = (const float*)d_in[18];
    const float* tqw    = (const float*)d_in[19];
    const float* tqb    = (const float*)d_in[20];
    const float* tkw    = (const float*)d_in[21];
    const float* tkb    = (const float*)d_in[22];
    const float* tvw    = (const float*)d_in[23];
    const float* tvb    = (const float*)d_in[24];
    const float* tow    = (const float*)d_in[25];
    const float* tob    = (const float*)d_in[26];
    const float* pw     = (const float*)d_in[27];
    const float* pb     = (const float*)d_in[28];
    float* out = (float*)d_out;

    float *ptable, *agg, *states, *tmp, *tmp2, *hid, *q, *k, *v, *mem, *mem2;
    cudaGetSymbolAddress((void**)&ptable, g_ptable);
    cudaGetSymbolAddress((void**)&agg,    g_agg);
    cudaGetSymbolAddress((void**)&states, g_states);
    cudaGetSymbolAddress((void**)&tmp,    g_tmp);
    cudaGetSymbolAddress((void**)&tmp2,   g_tmp2);
    cudaGetSymbolAddress((void**)&hid,    g_hid);
    cudaGetSymbolAddress((void**)&q,      g_q);
    cudaGetSymbolAddress((void**)&k,      g_k);
    cudaGetSymbolAddress((void**)&v,      g_v);
    cudaGetSymbolAddress((void**)&mem,    g_mem);
    cudaGetSymbolAddress((void**)&mem2,   g_mem2);

    // 1) project ALL relation embeddings once (33x FLOP cut vs per-gather proj)
    launch_gemm(rel_emb, rp_w, rp_b, ptable, Rsz, Dsz, RDsz, false);
    row_norm_kernel<<<Rsz, 128>>>();

    // 2) per-edge cosine sims, stable top-8, mean aggregate; states = rel_vec
    sim_topk_agg<<<BE, 256>>>(eids, nids);

    // 3) relation-context layers
    for (int l = 0; l < Lsz; l++) {
        launch_gemm(agg, vw + (size_t)l*Dsz*Dsz, vbp + l*Dsz, tmp,  BE, Dsz, Dsz, false);
        launch_gemm(tmp, ow + (size_t)l*Dsz*Dsz, obp + l*Dsz, tmp2, BE, Dsz, Dsz, false);
        add_ln<<<BE, 256>>>(states, tmp2, states, n1g + l*Dsz, n1b + l*Dsz, nullptr);
        launch_gemm(states, w1 + (size_t)l*4*Dsz*Dsz, b1 + l*4*Dsz, hid, BE, 4*Dsz, Dsz, true);
        launch_gemm(hid,    w2 + (size_t)l*Dsz*4*Dsz, b2 + l*Dsz,   tmp, BE, Dsz, 4*Dsz, false);
        add_ln<<<BE, 256>>>(states, tmp, states, n2g + l*Dsz, n2b + l*Dsz, mask);
    }

    // 4) memory tokenizer
    launch_gemm(mem_q,  tqw, tqb, q, Msz, Dsz, Dsz, false);
    launch_gemm(states, tkw, tkb, k, BE,  Dsz, Dsz, false);
    launch_gemm(states, tvw, tvb, v, BE,  Dsz, Dsz, false);
    mem_attn<<<Bsz*Msz, 256>>>(mask);
    launch_gemm(mem, tow, tob, mem2, Bsz*Msz, Dsz, Dsz, false);
    zero_noedge<<<Bsz, 256>>>(mask);

    // 5) final projection to LLM hidden size
    launch_gemm(mem2, pw, pb, out, Bsz*Msz, HLLMsz, Dsz, false);
}

// round 3
// speedup vs baseline: 2.2354x; 2.2354x over previous
#include <cuda_runtime.h>
#include <cuda_bf16.h>
#include <math.h>
#include <stdint.h>

// Problem constants
#define Bsz   8
#define Esz   256
#define Nsz   32
#define Dsz   512
#define RDsz  768
#define Rsz   2000
#define Lsz   2
#define Ksel  8
#define Msz   32
#define Hsz   8
#define DHsz  64
#define HLLMsz 4096
#define BE    (Bsz*Esz)   // 2048

// Scratch (static device globals; no allocation at runtime)
__device__ float g_ptable[Rsz*Dsz];
__device__ float g_norms[Rsz];
__device__ float g_agg[BE*Dsz];
__device__ float g_states[BE*Dsz];
__device__ float g_tmp[BE*Dsz];
__device__ float g_tmp2[BE*Dsz];
__device__ float g_hid[BE*4*Dsz];
__device__ float g_q[Msz*Dsz];
__device__ float g_k[BE*Dsz];
__device__ float g_v[BE*Dsz];
__device__ float g_mem[Bsz*Msz*Dsz];
__device__ float g_mem2[Bsz*Msz*Dsz];

// ---------------------------------------------------------------------------
// bf16x3 emulated-fp32 GEMM on mma.sync.m16n8k16 (legacy tensor path, valid
// for compute_103 generic PTX). C[M,N] = A[M,K] @ W[N,K]^T + bias (opt GELU).
// Block: 256 threads = 8 warps in a 4(m) x 2(n) grid.
// Warp tile: (MT*16) x (NT*8).  BM = 64*MT, BN = 16*NT, BK = 16.
// Smem: hi and lo bf16 tiles, row stride 12 words (conflict-free fragments).
// ---------------------------------------------------------------------------
__device__ __forceinline__ void mma_bf16(float* c, const uint32_t* a, const uint32_t* b)
{
    asm volatile(
        "mma.sync.aligned.m16n8k16.row.col.f32.bf16.bf16.f32 "
        "{%0,%1,%2,%3}, {%4,%5,%6,%7}, {%8,%9}, {%0,%1,%2,%3};"
        : "+f"(c[0]), "+f"(c[1]), "+f"(c[2]), "+f"(c[3])
        : "r"(a[0]), "r"(a[1]), "r"(a[2]), "r"(a[3]), "r"(b[0]), "r"(b[1]));
}

__device__ __forceinline__ void split2(float x, float y, uint32_t& hi, uint32_t& lo)
{
    __nv_bfloat162 h = __floats2bfloat162_rn(x, y);       // .x = x (low half)
    float2 hf = __bfloat1622float2(h);
    __nv_bfloat162 l = __floats2bfloat162_rn(x - hf.x, y - hf.y);
    hi = *reinterpret_cast<uint32_t*>(&h);
    lo = *reinterpret_cast<uint32_t*>(&l);
}

template<int MT, int NT, bool GELU>
__global__ __launch_bounds__(256)
void mma_gemm(const float* __restrict__ A, const float* __restrict__ W,
              const float* __restrict__ bias, float* __restrict__ C,
              int Mm, int Nn, int Kk)
{
    constexpr int BM = 64 * MT;
    constexpr int BN = 16 * NT;
    constexpr int ROWS = BM + BN;      // A rows then B rows in one staging space
    constexpr int CH = ROWS / 64;      // float4 chunks per thread per stage
    constexpr int STG = ROWS * 12;     // words per stage per (hi|lo) buffer

    extern __shared__ uint32_t sm[];
    uint32_t* sH = sm;                 // [2][STG]
    uint32_t* sL = sm + 2 * STG;       // [2][STG]

    const int tid  = threadIdx.x;
    const int wid  = tid >> 5;
    const int lane = tid & 31;
    const int m0 = blockIdx.y * BM;
    const int n0 = blockIdx.x * BN;
    const int mw = (wid >> 1) * (MT * 16);
    const int nw = (wid & 1) * (NT * 8);
    const int r  = lane >> 2;          // 0..7
    const int cq = lane & 3;           // 0..3

    float acc[MT][NT][4];
#pragma unroll
    for (int mt = 0; mt < MT; mt++)
#pragma unroll
        for (int j = 0; j < NT; j++)
#pragma unroll
            for (int t = 0; t < 4; t++) acc[mt][j][t] = 0.f;

    // staging assignment: chunk idx -> (row, q); row<BM => A row, else W row
    const float* gp[CH];
    int woff[CH];
    bool val[CH];
#pragma unroll
    for (int i = 0; i < CH; i++) {
        int idx = i * 256 + tid;       // 0 .. ROWS*4-1
        int row = idx >> 2;
        int q   = idx & 3;
        woff[i] = row * 12 + q * 2;
        if (row < BM) {
            gp[i]  = A + (size_t)(m0 + row) * Kk + q * 4;
            val[i] = (m0 + row) < Mm;
        } else {
            gp[i]  = W + (size_t)(n0 + row - BM) * Kk + q * 4;
            val[i] = true;
        }
    }

    float4 buf[CH];
#pragma unroll
    for (int i = 0; i < CH; i++)
        buf[i] = val[i] ? *(const float4*)gp[i] : make_float4(0.f, 0.f, 0.f, 0.f);
    // convert + store stage 0
#pragma unroll
    for (int i = 0; i < CH; i++) {
        uint32_t h0, l0, h1, l1;
        split2(buf[i].x, buf[i].y, h0, l0);
        split2(buf[i].z, buf[i].w, h1, l1);
        sH[woff[i]] = h0; sH[woff[i] + 1] = h1;
        sL[woff[i]] = l0; sL[woff[i] + 1] = l1;
    }
    __syncthreads();

    const int nkt = Kk >> 4;
    for (int kt = 0; kt < nkt; kt++) {
        const int s = kt & 1;
        if (kt + 1 < nkt) {
#pragma unroll
            for (int i = 0; i < CH; i++)
                buf[i] = val[i] ? *(const float4*)(gp[i] + (size_t)(kt + 1) * 16)
                                : make_float4(0.f, 0.f, 0.f, 0.f);
        }
        const uint32_t* H  = sH + s * STG;
        const uint32_t* Lo = sL + s * STG;
        // A fragments (hi and lo)
        uint32_t ah[MT][4], al[MT][4];
#pragma unroll
        for (int mt = 0; mt < MT; mt++) {
            int ar = mw + mt * 16 + r;
            int b0 = ar * 12 + cq;
            ah[mt][0] = H[b0];           ah[mt][1] = H[b0 + 96];
            ah[mt][2] = H[b0 + 4];       ah[mt][3] = H[b0 + 100];
            al[mt][0] = Lo[b0];          al[mt][1] = Lo[b0 + 96];
            al[mt][2] = Lo[b0 + 4];      al[mt][3] = Lo[b0 + 100];
        }
#pragma unroll
        for (int j = 0; j < NT; j++) {
            int br = BM + nw + j * 8 + r;
            int bb = br * 12 + cq;
            uint32_t bh[2] = { H[bb],  H[bb + 4]  };
            uint32_t bl[2] = { Lo[bb], Lo[bb + 4] };
#pragma unroll
            for (int mt = 0; mt < MT; mt++) {
                mma_bf16(acc[mt][j], ah[mt], bh);
                mma_bf16(acc[mt][j], al[mt], bh);
                mma_bf16(acc[mt][j], ah[mt], bl);
            }
        }
        if (kt + 1 < nkt) {
            uint32_t* Hn  = sH + (s ^ 1) * STG;
            uint32_t* Lon = sL + (s ^ 1) * STG;
#pragma unroll
            for (int i = 0; i < CH; i++) {
                uint32_t h0, l0, h1, l1;
                split2(buf[i].x, buf[i].y, h0, l0);
                split2(buf[i].z, buf[i].w, h1, l1);
                Hn[woff[i]] = h0; Hn[woff[i] + 1] = h1;
                Lon[woff[i]] = l0; Lon[woff[i] + 1] = l1;
            }
        }
        __syncthreads();
    }

    // epilogue: bias (+GELU), guarded stores
#pragma unroll
    for (int mt = 0; mt < MT; mt++) {
#pragma unroll
        for (int j = 0; j < NT; j++) {
            int row0 = m0 + mw + mt * 16 + r;
            int col  = n0 + nw + j * 8 + cq * 2;
            float b0v = __ldg(&bias[col]);
            float b1v = __ldg(&bias[col + 1]);
            float v0 = acc[mt][j][0] + b0v;
            float v1 = acc[mt][j][1] + b1v;
            float v2 = acc[mt][j][2] + b0v;
            float v3 = acc[mt][j][3] + b1v;
            if (GELU) {
                v0 = 0.5f * v0 * (1.f + erff(v0 * 0.70710678118654752f));
                v1 = 0.5f * v1 * (1.f + erff(v1 * 0.70710678118654752f));
                v2 = 0.5f * v2 * (1.f + erff(v2 * 0.70710678118654752f));
                v3 = 0.5f * v3 * (1.f + erff(v3 * 0.70710678118654752f));
            }
            if (row0 < Mm) {
                float* cp = C + (size_t)row0 * Nn + col;
                cp[0] = v0; cp[1] = v1;
            }
            if (row0 + 8 < Mm) {
                float* cp = C + (size_t)(row0 + 8) * Nn + col;
                cp[0] = v2; cp[1] = v3;
            }
        }
    }
}

// ---------------------------------------------------------------------------
__device__ __forceinline__ float block_sum_256(float v, float* red)
{
    for (int o = 16; o; o >>= 1) v += __shfl_xor_sync(0xffffffffu, v, o);
    int w = threadIdx.x >> 5;
    if ((threadIdx.x & 31) == 0) red[w] = v;
    __syncthreads();
    float r = 0.f;
    if (threadIdx.x < 8) {
        r = red[threadIdx.x];
        for (int o = 4; o; o >>= 1) r += __shfl_xor_sync(0xffu, r, o);
        if (threadIdx.x == 0) red[0] = r;
    }
    __syncthreads();
    r = red[0];
    __syncthreads();
    return r;
}

__global__ __launch_bounds__(128)
void row_norm_kernel()
{
    int r = blockIdx.x;
    int tid = threadIdx.x;
    float s = 0.f;
#pragma unroll
    for (int d = tid; d < Dsz; d += 128) {
        float v = g_ptable[r*Dsz + d];
        s = fmaf(v, v, s);
    }
    for (int o = 16; o; o >>= 1) s += __shfl_xor_sync(0xffffffffu, s, o);
    __shared__ float red[4];
    if ((tid & 31) == 0) red[tid >> 5] = s;
    __syncthreads();
    if (tid == 0)
        g_norms[r] = sqrtf(red[0] + red[1] + red[2] + red[3]);
}

__global__ __launch_bounds__(256)
void sim_topk_agg(const int* __restrict__ eids, const int* __restrict__ nids)
{
    int be = blockIdx.x;
    int tid = threadIdx.x;
    __shared__ float ev[Dsz];
    __shared__ float sims[Nsz];
    __shared__ int   selnid[Ksel];
    int eid = eids[be];
    for (int d = tid; d < Dsz; d += 256) ev[d] = g_ptable[eid*Dsz + d];
    __syncthreads();
    float enorm = fmaxf(g_norms[eid], 1e-12f);
    int warp = tid >> 5, lane = tid & 31;
#pragma unroll
    for (int t = 0; t < 4; t++) {
        int n = warp*4 + t;
        int nid = nids[be*Nsz + n];
        const float* nv = &g_ptable[nid*Dsz];
        float s = 0.f;
#pragma unroll 4
        for (int d = lane; d < Dsz; d += 32) s = fmaf(nv[d], ev[d], s);
        for (int o = 16; o; o >>= 1) s += __shfl_xor_sync(0xffffffffu, s, o);
        if (lane == 0)
            sims[n] = s / (enorm * fmaxf(g_norms[nid], 1e-12f));
    }
    __syncthreads();
    if (tid == 0) {
        unsigned used = 0;
        for (int j = 0; j < Ksel; j++) {
            float best = -3.402823466e38f; int bi = 0;
            for (int n = 0; n < Nsz; n++)
                if (!((used >> n) & 1u) && sims[n] > best) { best = sims[n]; bi = n; }
            used |= 1u << bi;
            selnid[j] = nids[be*Nsz + bi];
        }
    }
    __syncthreads();
    for (int d = tid; d < Dsz; d += 256) {
        float s = 0.f;
#pragma unroll
        for (int j = 0; j < Ksel; j++) s += g_ptable[(size_t)selnid[j]*Dsz + d];
        g_agg[(size_t)be*Dsz + d]    = s * 0.125f;
        g_states[(size_t)be*Dsz + d] = ev[d];
    }
}

__global__ __launch_bounds__(256)
void add_ln(const float* __restrict__ x, const float* __restrict__ add,
            float* __restrict__ out, const float* __restrict__ g,
            const float* __restrict__ b, const float* __restrict__ mask)
{
    int row = blockIdx.x;
    int tid = threadIdx.x;
    __shared__ float red[8];
    size_t base = (size_t)row * Dsz;
    float v0 = x[base + tid]       + add[base + tid];
    float v1 = x[base + tid + 256] + add[base + tid + 256];
    float total = block_sum_256(v0 + v1, red);
    float mu = total * (1.f / Dsz);
    float d0 = v0 - mu, d1 = v1 - mu;
    float var = block_sum_256(d0*d0 + d1*d1, red) * (1.f / Dsz);
    float inv = rsqrtf(var + 1e-5f);
    float mk = mask ? mask[row] : 1.f;
    out[base + tid]       = (d0 * inv * g[tid]       + b[tid])       * mk;
    out[base + tid + 256] = (d1 * inv * g[tid + 256] + b[tid + 256]) * mk;
}

__global__ __launch_bounds__(256)
void mem_attn(const float* __restrict__ mask)
{
    int b = blockIdx.x >> 5;
    int m = blockIdx.x & 31;
    int tid = threadIdx.x;
    __shared__ float qs[Dsz];
    __shared__ float sc[Hsz][Esz];
    qs[tid]       = g_q[m*Dsz + tid];
    qs[tid + 256] = g_q[m*Dsz + tid + 256];
    __syncthreads();
    {
        int e = tid;
        const float* kr = &g_k[((size_t)b*Esz + e)*Dsz];
        float mk = mask[b*Esz + e];
#pragma unroll
        for (int h = 0; h < Hsz; h++) {
            float s = 0.f;
#pragma unroll
            for (int d = 0; d < DHsz; d += 4) {
                float4 kq = *(const float4*)&kr[h*DHsz + d];
                float4 qq = *(const float4*)&qs[h*DHsz + d];
                s = fmaf(kq.x, qq.x, s); s = fmaf(kq.y, qq.y, s);
                s = fmaf(kq.z, qq.z, s); s = fmaf(kq.w, qq.w, s);
            }
            s *= 0.125f;
            sc[h][e] = (mk == 0.f) ? -3.402823466e38f : s;
        }
    }
    __syncthreads();
    {
        int w = tid >> 5, lane = tid & 31;
        float vals[8];
        float mx = -3.402823466e38f;
#pragma unroll
        for (int j = 0; j < 8; j++) { vals[j] = sc[w][lane + 32*j]; mx = fmaxf(mx, vals[j]); }
        for (int o = 16; o; o >>= 1) mx = fmaxf(mx, __shfl_xor_sync(0xffffffffu, mx, o));
        float sm = 0.f;
#pragma unroll
        for (int j = 0; j < 8; j++) { vals[j] = expf(vals[j] - mx); sm += vals[j]; }
        for (int o = 16; o; o >>= 1) sm += __shfl_xor_sync(0xffffffffu, sm, o);
        float inv = 1.f / sm;
#pragma unroll
        for (int j = 0; j < 8; j++) sc[w][lane + 32*j] = vals[j] * inv;
    }
    __syncthreads();
    float a0 = 0.f, a1 = 0.f;
    int od0 = tid, od1 = tid + 256;
    int h0 = od0 >> 6, h1 = od1 >> 6;
    for (int e = 0; e < Esz; e++) {
        const float* vr = &g_v[((size_t)b*Esz + e)*Dsz];
        a0 = fmaf(sc[h0][e], vr[od0], a0);
        a1 = fmaf(sc[h1][e], vr[od1], a1);
    }
    size_t ob = (size_t)blockIdx.x * Dsz;
    g_mem[ob + od0] = a0;
    g_mem[ob + od1] = a1;
}

__global__ __launch_bounds__(256)
void zero_noedge(const float* __restrict__ mask)
{
    int b = blockIdx.x;
    __shared__ float red[8];
    float total = block_sum_256(mask[b*Esz + threadIdx.x], red);
    if (total == 0.f) {
        for (int i = threadIdx.x; i < Msz*Dsz; i += 256)
            g_mem2[(size_t)b*Msz*Dsz + i] = 0.f;
    }
}

// ---------------------------------------------------------------------------
template<int MT, int NT, bool GELU>
static void run_gemm(const float* A, const float* W, const float* bias,
                     float* C, int M, int N, int K)
{
    constexpr int BM = 64 * MT;
    constexpr int BN = 16 * NT;
    constexpr int ROWS = BM + BN;
    const size_t smem = (size_t)ROWS * 12 * 4 * 2 * 2;   // words*4B * (hi,lo) * 2 stages
    cudaFuncSetAttribute(mma_gemm<MT, NT, GELU>,
                         cudaFuncAttributeMaxDynamicSharedMemorySize, (int)smem);
    dim3 grid(N / BN, (M + BM - 1) / BM);
    mma_gemm<MT, NT, GELU><<<grid, 256, smem>>>(A, W, bias, C, M, N, K);
}

extern "C" void kernel_launch(void* const* d_in, const int* in_sizes, int n_in,
                              void* d_out, int out_size)
{
    (void)in_sizes; (void)n_in; (void)out_size;
    const int*   eids   = (const int*)d_in[0];
    const int*   nids   = (const int*)d_in[1];
    const float* mask   = (const float*)d_in[2];
    const float* rel_emb= (const float*)d_in[3];
    const float* rp_w   = (const float*)d_in[4];
    const float* rp_b   = (const float*)d_in[5];
    const float* vw     = (const float*)d_in[6];
    const float* vbp    = (const float*)d_in[7];
    const float* ow     = (const float*)d_in[8];
    const float* obp    = (const float*)d_in[9];
    const float* n1g    = (const float*)d_in[10];
    const float* n1b    = (const float*)d_in[11];
    const float* n2g    = (const float*)d_in[12];
    const float* n2b    = (const float*)d_in[13];
    const float* w1     = (const float*)d_in[14];
    const float* b1     = (const float*)d_in[15];
    const float* w2     = (const float*)d_in[16];
    const float* b2     = (const float*)d_in[17];
    const float* mem_q  = (const float*)d_in[18];
    const float* tqw    = (const float*)d_in[19];
    const float* tqb    = (const float*)d_in[20];
    const float* tkw    = (const float*)d_in[21];
    const float* tkb    = (const float*)d_in[22];
    const float* tvw    = (const float*)d_in[23];
    const float* tvb    = (const float*)d_in[24];
    const float* tow    = (const float*)d_in[25];
    const float* tob    = (const float*)d_in[26];
    const float* pw     = (const float*)d_in[27];
    const float* pb     = (const float*)d_in[28];
    float* out = (float*)d_out;

    float *ptable, *agg, *states, *tmp, *tmp2, *hid, *q, *k, *v, *mem, *mem2;
    cudaGetSymbolAddress((void**)&ptable, g_ptable);
    cudaGetSymbolAddress((void**)&agg,    g_agg);
    cudaGetSymbolAddress((void**)&states, g_states);
    cudaGetSymbolAddress((void**)&tmp,    g_tmp);
    cudaGetSymbolAddress((void**)&tmp2,   g_tmp2);
    cudaGetSymbolAddress((void**)&hid,    g_hid);
    cudaGetSymbolAddress((void**)&q,      g_q);
    cudaGetSymbolAddress((void**)&k,      g_k);
    cudaGetSymbolAddress((void**)&v,      g_v);
    cudaGetSymbolAddress((void**)&mem,    g_mem);
    cudaGetSymbolAddress((void**)&mem2,   g_mem2);

    // 1) project ALL relation embeddings once (33x FLOP cut vs per-gather proj)
    run_gemm<1,4,false>(rel_emb, rp_w, rp_b, ptable, Rsz, Dsz, RDsz);
    row_norm_kernel<<<Rsz, 128>>>();

    // 2) per-edge cosine sims, stable top-8, mean aggregate; states = rel_vec
    sim_topk_agg<<<BE, 256>>>(eids, nids);

    // 3) relation-context layers
    for (int l = 0; l < Lsz; l++) {
        run_gemm<1,4,false>(agg, vw + (size_t)l*Dsz*Dsz, vbp + l*Dsz, tmp,  BE, Dsz, Dsz);
        run_gemm<1,4,false>(tmp, ow + (size_t)l*Dsz*Dsz, obp + l*Dsz, tmp2, BE, Dsz, Dsz);
        add_ln<<<BE, 256>>>(states, tmp2, states, n1g + l*Dsz, n1b + l*Dsz, nullptr);
        run_gemm<2,4,true >(states, w1 + (size_t)l*4*Dsz*Dsz, b1 + l*4*Dsz, hid, BE, 4*Dsz, Dsz);
        run_gemm<2,4,false>(hid,    w2 + (size_t)l*Dsz*4*Dsz, b2 + l*Dsz,   tmp, BE, Dsz, 4*Dsz);
        add_ln<<<BE, 256>>>(states, tmp, states, n2g + l*Dsz, n2b + l*Dsz, mask);
    }

    // 4) memory tokenizer
    run_gemm<1,4,false>(mem_q,  tqw, tqb, q, Msz, Dsz, Dsz);
    run_gemm<1,4,false>(states, tkw, tkb, k, BE,  Dsz, Dsz);
    run_gemm<1,4,false>(states, tvw, tvb, v, BE,  Dsz, Dsz);
    mem_attn<<<Bsz*Msz, 256>>>(mask);
    run_gemm<1,4,false>(mem, tow, tob, mem2, Bsz*Msz, Dsz, Dsz);
    zero_noedge<<<Bsz, 256>>>(mask);

    // 5) final projection to LLM hidden size
    run_gemm<1,4,false>(mem2, pw, pb, out, Bsz*Msz, HLLMsz, Dsz);
}

// round 4
// speedup vs baseline: 2.9368x; 1.3137x over previous
#include <cuda_runtime.h>
#include <cuda_bf16.h>
#include <math.h>
#include <stdint.h>

// Problem constants
#define Bsz   8
#define Esz   256
#define Nsz   32
#define Dsz   512
#define RDsz  768
#define Rsz   2000
#define Lsz   2
#define Ksel  8
#define Msz   32
#define Hsz   8
#define DHsz  64
#define HLLMsz 4096
#define BE    (Bsz*Esz)   // 2048

// Scratch (static device globals; no allocation at runtime)
__device__ float g_ptable[Rsz*Dsz];
__device__ float g_norms[Rsz];
__device__ float g_agg[BE*Dsz];
__device__ float g_states[BE*Dsz];
__device__ float g_tmp[BE*Dsz];
__device__ float g_tmp2[BE*Dsz];
__device__ float g_hid[BE*4*Dsz];
__device__ float g_q[Msz*Dsz];
__device__ float g_k[BE*Dsz];
__device__ float g_v[BE*Dsz];
__device__ float g_mem[Bsz*Msz*Dsz];
__device__ float g_mem2[Bsz*Msz*Dsz];

// ---------------------------------------------------------------------------
__device__ __forceinline__ uint32_t smem_u32(const void* p) {
    uint32_t a;
    asm("{ .reg .u64 t; cvta.to.shared.u64 t, %1; cvt.u32.u64 %0, t; }"
        : "=r"(a) : "l"(p));
    return a;
}

__device__ __forceinline__ void mma_bf16(float* c, const uint32_t* a, const uint32_t* b)
{
    asm volatile(
        "mma.sync.aligned.m16n8k16.row.col.f32.bf16.bf16.f32 "
        "{%0,%1,%2,%3}, {%4,%5,%6,%7}, {%8,%9}, {%0,%1,%2,%3};"
        : "+f"(c[0]), "+f"(c[1]), "+f"(c[2]), "+f"(c[3])
        : "r"(a[0]), "r"(a[1]), "r"(a[2]), "r"(a[3]), "r"(b[0]), "r"(b[1]));
}

__device__ __forceinline__ void ldm4(uint32_t* d, uint32_t addr)
{
    asm volatile("ldmatrix.sync.aligned.m8n8.x4.shared.b16 {%0,%1,%2,%3}, [%4];"
        : "=r"(d[0]), "=r"(d[1]), "=r"(d[2]), "=r"(d[3]) : "r"(addr));
}

__device__ __forceinline__ void split2(float x, float y, uint32_t& hi, uint32_t& lo)
{
    __nv_bfloat162 h = __floats2bfloat162_rn(x, y);
    float2 hf = __bfloat1622float2(h);
    __nv_bfloat162 l = __floats2bfloat162_rn(x - hf.x, y - hf.y);
    hi = *reinterpret_cast<uint32_t*>(&h);
    lo = *reinterpret_cast<uint32_t*>(&l);
}

// ---------------------------------------------------------------------------
// bf16x3 emulated-fp32 GEMM on mma.sync.m16n8k16 + ldmatrix.x4.
// C[M,N] = A[M,K] @ W[N,K]^T + bias (opt exact GELU).
// Block: 256 threads = 8 warps as 4(m) x 2(n). BM=64, BN=NT*16, BK=32.
// Smem: 64B rows (32 bf16), chunk swizzle c' = c ^ ((row>>1)&3); hi & lo
// buffers, double-buffered. ldmatrix phases verified bank-conflict-free.
// ---------------------------------------------------------------------------
template<int NT, bool GELU>
__global__ __launch_bounds__(256)
void mma_gemm(const float* __restrict__ A, const float* __restrict__ W,
              const float* __restrict__ bias, float* __restrict__ C,
              int Mm, int Nn, int Kk)
{
    constexpr int BN    = NT * 16;
    constexpr int ROWS  = 64 + BN;       // A rows then W rows
    constexpr int CHv   = ROWS / 32;     // float4 chunks per thread per stage
    constexpr int BUF   = ROWS * 64;     // bytes per (stage,hi/lo) buffer
    constexpr int PAIRS = NT / 2;

    extern __shared__ char smraw[];
    const uint32_t sbase = smem_u32(smraw);

    const int tid  = threadIdx.x;
    const int lane = tid & 31;
    const int wid  = tid >> 5;
    const int m0 = blockIdx.y * 64;
    const int n0 = blockIdx.x * BN;
    const int mw = (wid >> 1) * 16;      // 4 m-warps
    const int nw = (wid & 1) * (NT * 8); // 2 n-warps
    const int r  = lane >> 2;
    const int cq = lane & 3;

    float acc[NT][4];
#pragma unroll
    for (int j = 0; j < NT; j++)
#pragma unroll
        for (int t = 0; t < 4; t++) acc[j][t] = 0.f;

    // staging assignment
    const float* gp[CHv];
    bool val[CHv];
    uint32_t soff[CHv];
#pragma unroll
    for (int i = 0; i < CHv; i++) {
        int idx = i * 256 + tid;         // 0 .. ROWS*8-1
        int rr  = idx >> 3;
        int q   = idx & 7;
        soff[i] = (uint32_t)(rr * 64 + (((q >> 1) ^ ((rr >> 1) & 3)) * 16) + (q & 1) * 8);
        if (rr < 64) {
            gp[i]  = A + (size_t)(m0 + rr) * Kk + q * 4;
            val[i] = (m0 + rr) < Mm;
        } else {
            gp[i]  = W + (size_t)(n0 + rr - 64) * Kk + q * 4;
            val[i] = true;
        }
    }

    // ldmatrix lane addressing
    const int rrA = mw + ((lane >> 3) & 1) * 8 + (lane & 7);
    const uint32_t arow = (uint32_t)(rrA * 64);
    const int aswz = (rrA >> 1) & 3;
    const int akk  = lane >> 4;
    uint32_t brow[PAIRS];
    int bswz[PAIRS];
    const int bkk = (lane >> 3) & 1;
#pragma unroll
    for (int p = 0; p < PAIRS; p++) {
        int rrB = 64 + nw + (p * 2 + (lane >> 4)) * 8 + (lane & 7);
        brow[p] = (uint32_t)(rrB * 64);
        bswz[p] = (rrB >> 1) & 3;
    }

    // load + split stage 0
    float4 buf[CHv];
#pragma unroll
    for (int i = 0; i < CHv; i++)
        buf[i] = val[i] ? *(const float4*)gp[i] : make_float4(0.f, 0.f, 0.f, 0.f);
    {
        char* Hb = smraw;                // stage0 hi
        char* Lb = smraw + BUF;          // stage0 lo
#pragma unroll
        for (int i = 0; i < CHv; i++) {
            uint32_t h0, l0, h1, l1;
            split2(buf[i].x, buf[i].y, h0, l0);
            split2(buf[i].z, buf[i].w, h1, l1);
            *(uint2*)(Hb + soff[i]) = make_uint2(h0, h1);
            *(uint2*)(Lb + soff[i]) = make_uint2(l0, l1);
        }
    }
    __syncthreads();

    const int nkt = Kk >> 5;             // BK = 32
    for (int kt = 0; kt < nkt; kt++) {
        const int s = kt & 1;
        if (kt + 1 < nkt) {
#pragma unroll
            for (int i = 0; i < CHv; i++)
                buf[i] = val[i] ? *(const float4*)(gp[i] + (size_t)(kt + 1) * 32)
                                : make_float4(0.f, 0.f, 0.f, 0.f);
        }
        const uint32_t Hb = sbase + (uint32_t)(s * 2) * BUF;
        const uint32_t Lb = Hb + BUF;
#pragma unroll
        for (int ks = 0; ks < 2; ks++) {
            uint32_t ah[4], al[4];
            const uint32_t ak = (uint32_t)(((ks * 2 + akk) ^ aswz) * 16);
            ldm4(ah, Hb + arow + ak);
            ldm4(al, Lb + arow + ak);
#pragma unroll
            for (int p = 0; p < PAIRS; p++) {
                uint32_t bh[4], bl[4];
                const uint32_t bk = (uint32_t)(((ks * 2 + bkk) ^ bswz[p]) * 16);
                ldm4(bh, Hb + brow[p] + bk);
                ldm4(bl, Lb + brow[p] + bk);
#pragma unroll
                for (int t = 0; t < 2; t++) {
                    const int j = p * 2 + t;
                    mma_bf16(acc[j], ah, bh + 2 * t);
                    mma_bf16(acc[j], al, bh + 2 * t);
                    mma_bf16(acc[j], ah, bl + 2 * t);
                }
            }
        }
        if (kt + 1 < nkt) {
            char* Hn = smraw + (size_t)((s ^ 1) * 2) * BUF;
            char* Ln = Hn + BUF;
#pragma unroll
            for (int i = 0; i < CHv; i++) {
                uint32_t h0, l0, h1, l1;
                split2(buf[i].x, buf[i].y, h0, l0);
                split2(buf[i].z, buf[i].w, h1, l1);
                *(uint2*)(Hn + soff[i]) = make_uint2(h0, h1);
                *(uint2*)(Ln + soff[i]) = make_uint2(l0, l1);
            }
        }
        __syncthreads();
    }

    // epilogue
    const int row0 = m0 + mw + r;
#pragma unroll
    for (int j = 0; j < NT; j++) {
        const int col = n0 + nw + j * 8 + cq * 2;
        const float b0v = __ldg(&bias[col]);
        const float b1v = __ldg(&bias[col + 1]);
        float v0 = acc[j][0] + b0v;
        float v1 = acc[j][1] + b1v;
        float v2 = acc[j][2] + b0v;
        float v3 = acc[j][3] + b1v;
        if (GELU) {
            v0 = 0.5f * v0 * (1.f + erff(v0 * 0.70710678118654752f));
            v1 = 0.5f * v1 * (1.f + erff(v1 * 0.70710678118654752f));
            v2 = 0.5f * v2 * (1.f + erff(v2 * 0.70710678118654752f));
            v3 = 0.5f * v3 * (1.f + erff(v3 * 0.70710678118654752f));
        }
        if (row0 < Mm) {
            float* cp = C + (size_t)row0 * Nn + col;
            cp[0] = v0; cp[1] = v1;
        }
        if (row0 + 8 < Mm) {
            float* cp = C + (size_t)(row0 + 8) * Nn + col;
            cp[0] = v2; cp[1] = v3;
        }
    }
}

// ---------------------------------------------------------------------------
__device__ __forceinline__ float block_sum_256(float v, float* red)
{
    for (int o = 16; o; o >>= 1) v += __shfl_xor_sync(0xffffffffu, v, o);
    int w = threadIdx.x >> 5;
    if ((threadIdx.x & 31) == 0) red[w] = v;
    __syncthreads();
    float r = 0.f;
    if (threadIdx.x < 8) {
        r = red[threadIdx.x];
        for (int o = 4; o; o >>= 1) r += __shfl_xor_sync(0xffu, r, o);
        if (threadIdx.x == 0) red[0] = r;
    }
    __syncthreads();
    r = red[0];
    __syncthreads();
    return r;
}

__global__ __launch_bounds__(128)
void row_norm_kernel()
{
    int r = blockIdx.x;
    int tid = threadIdx.x;
    float s = 0.f;
#pragma unroll
    for (int d = tid; d < Dsz; d += 128) {
        float v = g_ptable[r*Dsz + d];
        s = fmaf(v, v, s);
    }
    for (int o = 16; o; o >>= 1) s += __shfl_xor_sync(0xffffffffu, s, o);
    __shared__ float red[4];
    if ((tid & 31) == 0) red[tid >> 5] = s;
    __syncthreads();
    if (tid == 0)
        g_norms[r] = sqrtf(red[0] + red[1] + red[2] + red[3]);
}

__global__ __launch_bounds__(256)
void sim_topk_agg(const int* __restrict__ eids, const int* __restrict__ nids)
{
    int be = blockIdx.x;
    int tid = threadIdx.x;
    __shared__ float ev[Dsz];
    __shared__ float sims[Nsz];
    __shared__ int   selnid[Ksel];
    int eid = eids[be];
    for (int d = tid; d < Dsz; d += 256) ev[d] = g_ptable[eid*Dsz + d];
    __syncthreads();
    float enorm = fmaxf(g_norms[eid], 1e-12f);
    int warp = tid >> 5, lane = tid & 31;
#pragma unroll
    for (int t = 0; t < 4; t++) {
        int n = warp*4 + t;
        int nid = nids[be*Nsz + n];
        const float* nv = &g_ptable[nid*Dsz];
        float s = 0.f;
#pragma unroll 4
        for (int d = lane; d < Dsz; d += 32) s = fmaf(nv[d], ev[d], s);
        for (int o = 16; o; o >>= 1) s += __shfl_xor_sync(0xffffffffu, s, o);
        if (lane == 0)
            sims[n] = s / (enorm * fmaxf(g_norms[nid], 1e-12f));
    }
    __syncthreads();
    if (tid == 0) {
        unsigned used = 0;
        for (int j = 0; j < Ksel; j++) {
            float best = -3.402823466e38f; int bi = 0;
            for (int n = 0; n < Nsz; n++)
                if (!((used >> n) & 1u) && sims[n] > best) { best = sims[n]; bi = n; }
            used |= 1u << bi;
            selnid[j] = nids[be*Nsz + bi];
        }
    }
    __syncthreads();
    for (int d = tid; d < Dsz; d += 256) {
        float s = 0.f;
#pragma unroll
        for (int j = 0; j < Ksel; j++) s += g_ptable[(size_t)selnid[j]*Dsz + d];
        g_agg[(size_t)be*Dsz + d]    = s * 0.125f;
        g_states[(size_t)be*Dsz + d] = ev[d];
    }
}

__global__ __launch_bounds__(256)
void add_ln(const float* __restrict__ x, const float* __restrict__ add,
            float* __restrict__ out, const float* __restrict__ g,
            const float* __restrict__ b, const float* __restrict__ mask)
{
    int row = blockIdx.x;
    int tid = threadIdx.x;
    __shared__ float red[8];
    size_t base = (size_t)row * Dsz;
    float v0 = x[base + tid]       + add[base + tid];
    float v1 = x[base + tid + 256] + add[base + tid + 256];
    float total = block_sum_256(v0 + v1, red);
    float mu = total * (1.f / Dsz);
    float d0 = v0 - mu, d1 = v1 - mu;
    float var = block_sum_256(d0*d0 + d1*d1, red) * (1.f / Dsz);
    float inv = rsqrtf(var + 1e-5f);
    float mk = mask ? mask[row] : 1.f;
    out[base + tid]       = (d0 * inv * g[tid]       + b[tid])       * mk;
    out[base + tid + 256] = (d1 * inv * g[tid + 256] + b[tid + 256]) * mk;
}

__global__ __launch_bounds__(256)
void mem_attn(const float* __restrict__ mask)
{
    int b = blockIdx.x >> 5;
    int m = blockIdx.x & 31;
    int tid = threadIdx.x;
    __shared__ float qs[Dsz];
    __shared__ float sc[Hsz][Esz];
    qs[tid]       = g_q[m*Dsz + tid];
    qs[tid + 256] = g_q[m*Dsz + tid + 256];
    __syncthreads();
    {
        int e = tid;
        const float* kr = &g_k[((size_t)b*Esz + e)*Dsz];
        float mk = mask[b*Esz + e];
#pragma unroll
        for (int h = 0; h < Hsz; h++) {
            float s = 0.f;
#pragma unroll
            for (int d = 0; d < DHsz; d += 4) {
                float4 kq = *(const float4*)&kr[h*DHsz + d];
                float4 qq = *(const float4*)&qs[h*DHsz + d];
                s = fmaf(kq.x, qq.x, s); s = fmaf(kq.y, qq.y, s);
                s = fmaf(kq.z, qq.z, s); s = fmaf(kq.w, qq.w, s);
            }
            s *= 0.125f;
            sc[h][e] = (mk == 0.f) ? -3.402823466e38f : s;
        }
    }
    __syncthreads();
    {
        int w = tid >> 5, lane = tid & 31;
        float vals[8];
        float mx = -3.402823466e38f;
#pragma unroll
        for (int j = 0; j < 8; j++) { vals[j] = sc[w][lane + 32*j]; mx = fmaxf(mx, vals[j]); }
        for (int o = 16; o; o >>= 1) mx = fmaxf(mx, __shfl_xor_sync(0xffffffffu, mx, o));
        float sm = 0.f;
#pragma unroll
        for (int j = 0; j < 8; j++) { vals[j] = expf(vals[j] - mx); sm += vals[j]; }
        for (int o = 16; o; o >>= 1) sm += __shfl_xor_sync(0xffffffffu, sm, o);
        float inv = 1.f / sm;
#pragma unroll
        for (int j = 0; j < 8; j++) sc[w][lane + 32*j] = vals[j] * inv;
    }
    __syncthreads();
    float a0 = 0.f, a1 = 0.f;
    int od0 = tid, od1 = tid + 256;
    int h0 = od0 >> 6, h1 = od1 >> 6;
    for (int e = 0; e < Esz; e++) {
        const float* vr = &g_v[((size_t)b*Esz + e)*Dsz];
        a0 = fmaf(sc[h0][e], vr[od0], a0);
        a1 = fmaf(sc[h1][e], vr[od1], a1);
    }
    size_t ob = (size_t)blockIdx.x * Dsz;
    g_mem[ob + od0] = a0;
    g_mem[ob + od1] = a1;
}

__global__ __launch_bounds__(256)
void zero_noedge(const float* __restrict__ mask)
{
    int b = blockIdx.x;
    __shared__ float red[8];
    float total = block_sum_256(mask[b*Esz + threadIdx.x], red);
    if (total == 0.f) {
        for (int i = threadIdx.x; i < Msz*Dsz; i += 256)
            g_mem2[(size_t)b*Msz*Dsz + i] = 0.f;
    }
}

// ---------------------------------------------------------------------------
template<int NT, bool GELU>
static void run_gemm(const float* A, const float* W, const float* bias,
                     float* C, int M, int N, int K)
{
    constexpr int BN = NT * 16;
    constexpr int ROWS = 64 + BN;
    const size_t smem = (size_t)ROWS * 256;   // 4 buffers * ROWS*64B
    cudaFuncSetAttribute(mma_gemm<NT, GELU>,
                         cudaFuncAttributeMaxDynamicSharedMemorySize, (int)smem);
    dim3 grid(N / BN, (M + 63) / 64);
    mma_gemm<NT, GELU><<<grid, 256, smem>>>(A, W, bias, C, M, N, K);
}

extern "C" void kernel_launch(void* const* d_in, const int* in_sizes, int n_in,
                              void* d_out, int out_size)
{
    (void)in_sizes; (void)n_in; (void)out_size;
    const int*   eids   = (const int*)d_in[0];
    const int*   nids   = (const int*)d_in[1];
    const float* mask   = (const float*)d_in[2];
    const float* rel_emb= (const float*)d_in[3];
    const float* rp_w   = (const float*)d_in[4];
    const float* rp_b   = (const float*)d_in[5];
    const float* vw     = (const float*)d_in[6];
    const float* vbp    = (const float*)d_in[7];
    const float* ow     = (const float*)d_in[8];
    const float* obp    = (const float*)d_in[9];
    const float* n1g    = (const float*)d_in[10];
    const float* n1b    = (const float*)d_in[11];
    const float* n2g    = (const float*)d_in[12];
    const float* n2b    = (const float*)d_in[13];
    const float* w1     = (const float*)d_in[14];
    const float* b1     = (const float*)d_in[15];
    const float* w2     = (const float*)d_in[16];
    const float* b2     = (const float*)d_in[17];
    const float* mem_q  = (const float*)d_in[18];
    const float* tqw    = (const float*)d_in[19];
    const float* tqb    = (const float*)d_in[20];
    const float* tkw    = (const float*)d_in[21];
    const float* tkb    = (const float*)d_in[22];
    const float* tvw    = (const float*)d_in[23];
    const float* tvb    = (const float*)d_in[24];
    const float* tow    = (const float*)d_in[25];
    const float* tob    = (const float*)d_in[26];
    const float* pw     = (const float*)d_in[27];
    const float* pb     = (const float*)d_in[28];
    float* out = (float*)d_out;

    float *ptable, *agg, *states, *tmp, *tmp2, *hid, *q, *k, *v, *mem, *mem2;
    cudaGetSymbolAddress((void**)&ptable, g_ptable);
    cudaGetSymbolAddress((void**)&agg,    g_agg);
    cudaGetSymbolAddress((void**)&states, g_states);
    cudaGetSymbolAddress((void**)&tmp,    g_tmp);
    cudaGetSymbolAddress((void**)&tmp2,   g_tmp2);
    cudaGetSymbolAddress((void**)&hid,    g_hid);
    cudaGetSymbolAddress((void**)&q,      g_q);
    cudaGetSymbolAddress((void**)&k,      g_k);
    cudaGetSymbolAddress((void**)&v,      g_v);
    cudaGetSymbolAddress((void**)&mem,    g_mem);
    cudaGetSymbolAddress((void**)&mem2,   g_mem2);

    // 1) project ALL relation embeddings once (33x FLOP cut vs per-gather proj)
    run_gemm<4,false>(rel_emb, rp_w, rp_b, ptable, Rsz, Dsz, RDsz);
    row_norm_kernel<<<Rsz, 128>>>();

    // 2) per-edge cosine sims, stable top-8, mean aggregate; states = rel_vec
    sim_topk_agg<<<BE, 256>>>(eids, nids);

    // 3) relation-context layers
    for (int l = 0; l < Lsz; l++) {
        run_gemm<4,false>(agg, vw + (size_t)l*Dsz*Dsz, vbp + l*Dsz, tmp,  BE, Dsz, Dsz);
        run_gemm<4,false>(tmp, ow + (size_t)l*Dsz*Dsz, obp + l*Dsz, tmp2, BE, Dsz, Dsz);
        add_ln<<<BE, 256>>>(states, tmp2, states, n1g + l*Dsz, n1b + l*Dsz, nullptr);
        run_gemm<8,true >(states, w1 + (size_t)l*4*Dsz*Dsz, b1 + l*4*Dsz, hid, BE, 4*Dsz, Dsz);
        run_gemm<4,false>(hid,    w2 + (size_t)l*Dsz*4*Dsz, b2 + l*Dsz,   tmp, BE, Dsz, 4*Dsz);
        add_ln<<<BE, 256>>>(states, tmp, states, n2g + l*Dsz, n2b + l*Dsz, mask);
    }

    // 4) memory tokenizer
    run_gemm<4,false>(mem_q,  tqw, tqb, q, Msz, Dsz, Dsz);
    run_gemm<4,false>(states, tkw, tkb, k, BE,  Dsz, Dsz);
    run_gemm<4,false>(states, tvw, tvb, v, BE,  Dsz, Dsz);
    mem_attn<<<Bsz*Msz, 256>>>(mask);
    run_gemm<4,false>(mem, tow, tob, mem2, Bsz*Msz, Dsz, Dsz);
    zero_noedge<<<Bsz, 256>>>(mask);

    // 5) final projection to LLM hidden size
    run_gemm<8,false>(mem2, pw, pb, out, Bsz*Msz, HLLMsz, Dsz);
}

// round 5
// speedup vs baseline: 3.1786x; 1.0823x over previous
#include <cuda_runtime.h>
#include <cuda_bf16.h>
#include <math.h>
#include <stdint.h>

// Problem constants
#define Bsz   8
#define Esz   256
#define Nsz   32
#define Dsz   512
#define RDsz  768
#define Rsz   2000
#define Lsz   2
#define Ksel  8
#define Msz   32
#define Hsz   8
#define DHsz  64
#define HLLMsz 4096
#define BE    (Bsz*Esz)   // 2048

// fp32 scratch
__device__ float g_ptable[Rsz*Dsz];
__device__ float g_norms[Rsz];
__device__ float g_states[BE*Dsz];
__device__ float g_tmp[BE*Dsz];
__device__ float g_tmp2[BE*Dsz];
__device__ float g_q[Msz*Dsz];
__device__ float g_k[BE*Dsz];
__device__ float g_v[BE*Dsz];

// bf16 hi/lo split scratch
__device__ __nv_bfloat16 g_relh[Rsz*RDsz],      g_rell[Rsz*RDsz];
__device__ __nv_bfloat16 g_rpwh[Dsz*RDsz],      g_rpwl[Dsz*RDsz];
__device__ __nv_bfloat16 g_vwh[Lsz*Dsz*Dsz],    g_vwl[Lsz*Dsz*Dsz];
__device__ __nv_bfloat16 g_owh[Lsz*Dsz*Dsz],    g_owl[Lsz*Dsz*Dsz];
__device__ __nv_bfloat16 g_w1h[Lsz*4*Dsz*Dsz],  g_w1l[Lsz*4*Dsz*Dsz];
__device__ __nv_bfloat16 g_w2h[Lsz*4*Dsz*Dsz],  g_w2l[Lsz*4*Dsz*Dsz];
__device__ __nv_bfloat16 g_tqwh[Dsz*Dsz],       g_tqwl[Dsz*Dsz];
__device__ __nv_bfloat16 g_tkwh[Dsz*Dsz],       g_tkwl[Dsz*Dsz];
__device__ __nv_bfloat16 g_tvwh[Dsz*Dsz],       g_tvwl[Dsz*Dsz];
__device__ __nv_bfloat16 g_towh[Dsz*Dsz],       g_towl[Dsz*Dsz];
__device__ __nv_bfloat16 g_pwh[HLLMsz*Dsz],     g_pwl[HLLMsz*Dsz];
__device__ __nv_bfloat16 g_memqh[Msz*Dsz],      g_memql[Msz*Dsz];
__device__ __nv_bfloat16 g_aggh[BE*Dsz],        g_aggl[BE*Dsz];
__device__ __nv_bfloat16 g_sth[BE*Dsz],         g_stl[BE*Dsz];
__device__ __nv_bfloat16 g_tAh[BE*Dsz],         g_tAl[BE*Dsz];
__device__ __nv_bfloat16 g_hidh[BE*4*Dsz],      g_hidl[BE*4*Dsz];
__device__ __nv_bfloat16 g_memh[Bsz*Msz*Dsz],   g_meml[Bsz*Msz*Dsz];
__device__ __nv_bfloat16 g_m2h[Bsz*Msz*Dsz],    g_m2l[Bsz*Msz*Dsz];

// ---------------------------------------------------------------------------
__device__ __forceinline__ uint32_t smem_u32(const void* p) {
    uint32_t a;
    asm("{ .reg .u64 t; cvta.to.shared.u64 t, %1; cvt.u32.u64 %0, t; }"
        : "=r"(a) : "l"(p));
    return a;
}

__device__ __forceinline__ void mma_bf16(float* c, const uint32_t* a, const uint32_t* b)
{
    asm volatile(
        "mma.sync.aligned.m16n8k16.row.col.f32.bf16.bf16.f32 "
        "{%0,%1,%2,%3}, {%4,%5,%6,%7}, {%8,%9}, {%0,%1,%2,%3};"
        : "+f"(c[0]), "+f"(c[1]), "+f"(c[2]), "+f"(c[3])
        : "r"(a[0]), "r"(a[1]), "r"(a[2]), "r"(a[3]), "r"(b[0]), "r"(b[1]));
}

__device__ __forceinline__ void ldm4(uint32_t* d, uint32_t addr)
{
    asm volatile("ldmatrix.sync.aligned.m8n8.x4.shared.b16 {%0,%1,%2,%3}, [%4];"
        : "=r"(d[0]), "=r"(d[1]), "=r"(d[2]), "=r"(d[3]) : "r"(addr));
}

__device__ __forceinline__ void split2(float x, float y, uint32_t& hi, uint32_t& lo)
{
    __nv_bfloat162 h = __floats2bfloat162_rn(x, y);
    float2 hf = __bfloat1622float2(h);
    __nv_bfloat162 l = __floats2bfloat162_rn(x - hf.x, y - hf.y);
    hi = *reinterpret_cast<uint32_t*>(&h);
    lo = *reinterpret_cast<uint32_t*>(&l);
}

__device__ __forceinline__ void split_scalar(float v, __nv_bfloat16* hp, __nv_bfloat16* lp)
{
    __nv_bfloat16 h = __float2bfloat16(v);
    *hp = h;
    *lp = __float2bfloat16(v - __bfloat162float(h));
}

#define CP_ASYNC16(dst, src) \
    asm volatile("cp.async.cg.shared.global [%0], [%1], 16;" :: "r"(dst), "l"(src))
#define CP_COMMIT() asm volatile("cp.async.commit_group;" ::: "memory")

// ---------------------------------------------------------------------------
// Batched fp32 -> (hi,lo) bf16 split for all GEMM operands.
// ---------------------------------------------------------------------------
struct SJobs {
    const float4* src[12];
    uint2* hi[12];
    uint2* lo[12];
    unsigned end4[12];     // cumulative float4 counts
    int cnt;
    unsigned total4;
};

__global__ __launch_bounds__(256)
void split_multi(SJobs jb)
{
    unsigned idx = blockIdx.x * 256u + threadIdx.x;
    if (idx >= jb.total4) return;
    int t = 0;
    unsigned start = 0;
#pragma unroll 1
    for (int i = 0; i < jb.cnt; i++) {
        if (idx < jb.end4[i]) { t = i; break; }
        start = jb.end4[i];
    }
    // recompute start properly (start = end4[t-1])
    start = (t == 0) ? 0u : jb.end4[t - 1];
    unsigned li = idx - start;
    float4 v = jb.src[t][li];
    uint32_t h0, l0, h1, l1;
    split2(v.x, v.y, h0, l0);
    split2(v.z, v.w, h1, l1);
    jb.hi[t][li] = make_uint2(h0, h1);
    jb.lo[t][li] = make_uint2(l0, l1);
}

// ---------------------------------------------------------------------------
// bf16x3 emulated-fp32 GEMM on mma.sync.m16n8k16 + ldmatrix.x4 + cp.async.
// Operands are pre-split bf16 (hi, lo). C = A @ W^T + bias (opt exact GELU).
// Block: 256 threads = 8 warps as 4(m) x 2(n). BM=64, BN=NT*16, BK=32.
// Smem rows 64B (32 bf16), chunk swizzle q' = q ^ ((row>>1)&3); hi & lo
// buffers, double-buffered via cp.async groups.
// ---------------------------------------------------------------------------
template<int NT, bool GELU, bool WSPLIT, bool WF32>
__global__ __launch_bounds__(256)
void mma_gemm(const __nv_bfloat16* __restrict__ Ah, const __nv_bfloat16* __restrict__ Al,
              const __nv_bfloat16* __restrict__ Wh, const __nv_bfloat16* __restrict__ Wl,
              const float* __restrict__ bias, float* __restrict__ C,
              __nv_bfloat16* __restrict__ Chi, __nv_bfloat16* __restrict__ Clo,
              int Mm, int Nn, int Kk)
{
    constexpr int BN    = NT * 16;
    constexpr int ROWS  = 64 + BN;
    constexpr int CHc   = ROWS * 8 / 256;   // 16B cp.async chunks per thread
    constexpr int BUF   = ROWS * 64;        // bytes per (stage, hi/lo) buffer
    constexpr int PAIRS = NT / 2;

    extern __shared__ char smraw[];
    const uint32_t sbase = smem_u32(smraw);

    const int tid  = threadIdx.x;
    const int lane = tid & 31;
    const int wid  = tid >> 5;
    const int m0 = blockIdx.y * 64;
    const int n0 = blockIdx.x * BN;
    const int mw = (wid >> 1) * 16;
    const int nw = (wid & 1) * (NT * 8);
    const int r  = lane >> 2;
    const int cq = lane & 3;

    float acc[NT][4];
#pragma unroll
    for (int j = 0; j < NT; j++)
#pragma unroll
        for (int t = 0; t < 4; t++) acc[j][t] = 0.f;

    // staging: chunk idx over [hi: ROWS*4][lo: ROWS*4], 16B chunks
    const __nv_bfloat16* gp[CHc];
    bool val[CHc];
    uint32_t soff[CHc];
#pragma unroll
    for (int i = 0; i < CHc; i++) {
        int idx = i * 256 + tid;
        int b   = idx >= ROWS * 4;
        int rem = idx - b * ROWS * 4;
        int rr  = rem >> 2;
        int q   = rem & 3;
        soff[i] = (uint32_t)(b * BUF + rr * 64 + ((q ^ ((rr >> 1) & 3)) * 16));
        const __nv_bfloat16* src;
        int grow;
        if (rr < 64) { src = b ? Al : Ah; grow = m0 + rr; val[i] = grow < Mm; }
        else         { src = b ? Wl : Wh; grow = n0 + rr - 64; val[i] = true; }
        gp[i] = src + (size_t)grow * Kk + q * 8;
    }

    // ldmatrix lane addressing (same layout as before)
    const int rrA = mw + ((lane >> 3) & 1) * 8 + (lane & 7);
    const uint32_t arow = (uint32_t)(rrA * 64);
    const int aswz = (rrA >> 1) & 3;
    const int akk  = lane >> 4;
    uint32_t brow[PAIRS];
    int bswz[PAIRS];
    const int bkk = (lane >> 3) & 1;
#pragma unroll
    for (int p = 0; p < PAIRS; p++) {
        int rrB = 64 + nw + (p * 2 + (lane >> 4)) * 8 + (lane & 7);
        brow[p] = (uint32_t)(rrB * 64);
        bswz[p] = (rrB >> 1) & 3;
    }

    // prologue: stage 0
#pragma unroll
    for (int i = 0; i < CHc; i++)
        if (val[i]) CP_ASYNC16(sbase + soff[i], gp[i]);
    CP_COMMIT();

    const int nkt = Kk >> 5;            // BK = 32
#pragma unroll 1
    for (int kt = 0; kt < nkt; kt++) {
        const int s = kt & 1;
        if (kt + 1 < nkt) {
            const uint32_t dst = sbase + (uint32_t)((s ^ 1) * 2) * BUF;
            const size_t koff = (size_t)(kt + 1) * 32;
#pragma unroll
            for (int i = 0; i < CHc; i++)
                if (val[i]) CP_ASYNC16(dst + soff[i], gp[i] + koff);
            CP_COMMIT();
            asm volatile("cp.async.wait_group 1;" ::: "memory");
        } else {
            asm volatile("cp.async.wait_group 0;" ::: "memory");
        }
        __syncthreads();

        const uint32_t Hb = sbase + (uint32_t)(s * 2) * BUF;
        const uint32_t Lb = Hb + BUF;
#pragma unroll
        for (int ks = 0; ks < 2; ks++) {
            uint32_t ah[4], al[4];
            const uint32_t ak = (uint32_t)(((ks * 2 + akk) ^ aswz) * 16);
            ldm4(ah, Hb + arow + ak);
            ldm4(al, Lb + arow + ak);
#pragma unroll
            for (int p = 0; p < PAIRS; p++) {
                uint32_t bh[4], bl[4];
                const uint32_t bk = (uint32_t)(((ks * 2 + bkk) ^ bswz[p]) * 16);
                ldm4(bh, Hb + brow[p] + bk);
                ldm4(bl, Lb + brow[p] + bk);
#pragma unroll
                for (int t = 0; t < 2; t++) {
                    const int j = p * 2 + t;
                    mma_bf16(acc[j], ah, bh + 2 * t);
                    mma_bf16(acc[j], al, bh + 2 * t);
                    mma_bf16(acc[j], ah, bl + 2 * t);
                }
            }
        }
        __syncthreads();
    }

    // epilogue
    const int row0 = m0 + mw + r;
#pragma unroll
    for (int j = 0; j < NT; j++) {
        const int col = n0 + nw + j * 8 + cq * 2;
        const float b0v = __ldg(&bias[col]);
        const float b1v = __ldg(&bias[col + 1]);
        float v0 = acc[j][0] + b0v;
        float v1 = acc[j][1] + b1v;
        float v2 = acc[j][2] + b0v;
        float v3 = acc[j][3] + b1v;
        if (GELU) {
            v0 = 0.5f * v0 * (1.f + erff(v0 * 0.70710678118654752f));
            v1 = 0.5f * v1 * (1.f + erff(v1 * 0.70710678118654752f));
            v2 = 0.5f * v2 * (1.f + erff(v2 * 0.70710678118654752f));
            v3 = 0.5f * v3 * (1.f + erff(v3 * 0.70710678118654752f));
        }
        if (row0 < Mm) {
            const size_t o = (size_t)row0 * Nn + col;
            if (WF32) { C[o] = v0; C[o + 1] = v1; }
            if (WSPLIT) {
                uint32_t h, l; split2(v0, v1, h, l);
                *(uint32_t*)&Chi[o] = h; *(uint32_t*)&Clo[o] = l;
            }
        }
        if (row0 + 8 < Mm) {
            const size_t o = (size_t)(row0 + 8) * Nn + col;
            if (WF32) { C[o] = v2; C[o + 1] = v3; }
            if (WSPLIT) {
                uint32_t h, l; split2(v2, v3, h, l);
                *(uint32_t*)&Chi[o] = h; *(uint32_t*)&Clo[o] = l;
            }
        }
    }
}

// ---------------------------------------------------------------------------
__device__ __forceinline__ float block_sum_256(float v, float* red)
{
    for (int o = 16; o; o >>= 1) v += __shfl_xor_sync(0xffffffffu, v, o);
    int w = threadIdx.x >> 5;
    if ((threadIdx.x & 31) == 0) red[w] = v;
    __syncthreads();
    float r = 0.f;
    if (threadIdx.x < 8) {
        r = red[threadIdx.x];
        for (int o = 4; o; o >>= 1) r += __shfl_xor_sync(0xffu, r, o);
        if (threadIdx.x == 0) red[0] = r;
    }
    __syncthreads();
    r = red[0];
    __syncthreads();
    return r;
}

__global__ __launch_bounds__(128)
void row_norm_kernel()
{
    int r = blockIdx.x;
    int tid = threadIdx.x;
    float s = 0.f;
#pragma unroll
    for (int d = tid; d < Dsz; d += 128) {
        float v = g_ptable[r*Dsz + d];
        s = fmaf(v, v, s);
    }
    for (int o = 16; o; o >>= 1) s += __shfl_xor_sync(0xffffffffu, s, o);
    __shared__ float red[4];
    if ((tid & 31) == 0) red[tid >> 5] = s;
    __syncthreads();
    if (tid == 0)
        g_norms[r] = sqrtf(red[0] + red[1] + red[2] + red[3]);
}

__global__ __launch_bounds__(256)
void sim_topk_agg(const int* __restrict__ eids, const int* __restrict__ nids)
{
    int be = blockIdx.x;
    int tid = threadIdx.x;
    __shared__ float ev[Dsz];
    __shared__ float sims[Nsz];
    __shared__ int   selnid[Ksel];
    int eid = eids[be];
    for (int d = tid; d < Dsz; d += 256) ev[d] = g_ptable[eid*Dsz + d];
    __syncthreads();
    float enorm = fmaxf(g_norms[eid], 1e-12f);
    int warp = tid >> 5, lane = tid & 31;
#pragma unroll
    for (int t = 0; t < 4; t++) {
        int n = warp*4 + t;
        int nid = nids[be*Nsz + n];
        const float* nv = &g_ptable[nid*Dsz];
        float s = 0.f;
#pragma unroll 4
        for (int d = lane; d < Dsz; d += 32) s = fmaf(nv[d], ev[d], s);
        for (int o = 16; o; o >>= 1) s += __shfl_xor_sync(0xffffffffu, s, o);
        if (lane == 0)
            sims[n] = s / (enorm * fmaxf(g_norms[nid], 1e-12f));
    }
    __syncthreads();
    if (tid == 0) {
        unsigned used = 0;
        for (int j = 0; j < Ksel; j++) {
            float best = -3.402823466e38f; int bi = 0;
            for (int n = 0; n < Nsz; n++)
                if (!((used >> n) & 1u) && sims[n] > best) { best = sims[n]; bi = n; }
            used |= 1u << bi;
            selnid[j] = nids[be*Nsz + bi];
        }
    }
    __syncthreads();
    for (int d = tid; d < Dsz; d += 256) {
        float s = 0.f;
#pragma unroll
        for (int j = 0; j < Ksel; j++) s += g_ptable[(size_t)selnid[j]*Dsz + d];
        const size_t o = (size_t)be*Dsz + d;
        split_scalar(s * 0.125f, &g_aggh[o], &g_aggl[o]);
        g_states[o] = ev[d];
    }
}

// states = LN(x + add) * mask; writes fp32 + bf16 split
__global__ __launch_bounds__(256)
void add_ln(const float* __restrict__ x, const float* __restrict__ add,
            float* __restrict__ out, const float* __restrict__ g,
            const float* __restrict__ b, const float* __restrict__ mask)
{
    int row = blockIdx.x;
    int tid = threadIdx.x;
    __shared__ float red[8];
    size_t base = (size_t)row * Dsz;
    float v0 = x[base + tid]       + add[base + tid];
    float v1 = x[base + tid + 256] + add[base + tid + 256];
    float total = block_sum_256(v0 + v1, red);
    float mu = total * (1.f / Dsz);
    float d0 = v0 - mu, d1 = v1 - mu;
    float var = block_sum_256(d0*d0 + d1*d1, red) * (1.f / Dsz);
    float inv = rsqrtf(var + 1e-5f);
    float mk = mask ? mask[row] : 1.f;
    float o0 = (d0 * inv * g[tid]       + b[tid])       * mk;
    float o1 = (d1 * inv * g[tid + 256] + b[tid + 256]) * mk;
    out[base + tid]       = o0;
    out[base + tid + 256] = o1;
    split_scalar(o0, &g_sth[base + tid],       &g_stl[base + tid]);
    split_scalar(o1, &g_sth[base + tid + 256], &g_stl[base + tid + 256]);
}

__global__ __launch_bounds__(256)
void mem_attn(const float* __restrict__ mask)
{
    int b = blockIdx.x >> 5;
    int m = blockIdx.x & 31;
    int tid = threadIdx.x;
    __shared__ float qs[Dsz];
    __shared__ float sc[Hsz][Esz];
    qs[tid]       = g_q[m*Dsz + tid];
    qs[tid + 256] = g_q[m*Dsz + tid + 256];
    __syncthreads();
    {
        int e = tid;
        const float* kr = &g_k[((size_t)b*Esz + e)*Dsz];
        float mk = mask[b*Esz + e];
#pragma unroll
        for (int h = 0; h < Hsz; h++) {
            float s = 0.f;
#pragma unroll
            for (int d = 0; d < DHsz; d += 4) {
                float4 kq = *(const float4*)&kr[h*DHsz + d];
                float4 qq = *(const float4*)&qs[h*DHsz + d];
                s = fmaf(kq.x, qq.x, s); s = fmaf(kq.y, qq.y, s);
                s = fmaf(kq.z, qq.z, s); s = fmaf(kq.w, qq.w, s);
            }
            s *= 0.125f;
            sc[h][e] = (mk == 0.f) ? -3.402823466e38f : s;
        }
    }
    __syncthreads();
    {
        int w = tid >> 5, lane = tid & 31;
        float vals[8];
        float mx = -3.402823466e38f;
#pragma unroll
        for (int j = 0; j < 8; j++) { vals[j] = sc[w][lane + 32*j]; mx = fmaxf(mx, vals[j]); }
        for (int o = 16; o; o >>= 1) mx = fmaxf(mx, __shfl_xor_sync(0xffffffffu, mx, o));
        float sm = 0.f;
#pragma unroll
        for (int j = 0; j < 8; j++) { vals[j] = expf(vals[j] - mx); sm += vals[j]; }
        for (int o = 16; o; o >>= 1) sm += __shfl_xor_sync(0xffffffffu, sm, o);
        float inv = 1.f / sm;
#pragma unroll
        for (int j = 0; j < 8; j++) sc[w][lane + 32*j] = vals[j] * inv;
    }
    __syncthreads();
    float a0 = 0.f, a1 = 0.f;
    int od0 = tid, od1 = tid + 256;
    int h0 = od0 >> 6, h1 = od1 >> 6;
    for (int e = 0; e < Esz; e++) {
        const float* vr = &g_v[((size_t)b*Esz + e)*Dsz];
        a0 = fmaf(sc[h0][e], vr[od0], a0);
        a1 = fmaf(sc[h1][e], vr[od1], a1);
    }
    size_t ob = (size_t)blockIdx.x * Dsz;
    split_scalar(a0, &g_memh[ob + od0], &g_meml[ob + od0]);
    split_scalar(a1, &g_memh[ob + od1], &g_meml[ob + od1]);
}

__global__ __launch_bounds__(256)
void zero_noedge(const float* __restrict__ mask)
{
    int b = blockIdx.x;
    __shared__ float red[8];
    float total = block_sum_256(mask[b*Esz + threadIdx.x], red);
    if (total == 0.f) {
        uint32_t* h = (uint32_t*)&g_m2h[(size_t)b*Msz*Dsz];
        uint32_t* l = (uint32_t*)&g_m2l[(size_t)b*Msz*Dsz];
        for (int i = threadIdx.x; i < Msz*Dsz/2; i += 256) { h[i] = 0u; l[i] = 0u; }
    }
}

// ---------------------------------------------------------------------------
template<int NT, bool GELU, bool WSPLIT, bool WF32>
static void run_gemm(const __nv_bfloat16* Ah, const __nv_bfloat16* Al,
                     const __nv_bfloat16* Wh, const __nv_bfloat16* Wl,
                     const float* bias, float* C,
                     __nv_bfloat16* Chi, __nv_bfloat16* Clo,
                     int M, int N, int K)
{
    constexpr int BN = NT * 16;
    constexpr int ROWS = 64 + BN;
    const size_t smem = (size_t)ROWS * 256;   // 4 buffers * ROWS*64B
    cudaFuncSetAttribute(mma_gemm<NT, GELU, WSPLIT, WF32>,
                         cudaFuncAttributeMaxDynamicSharedMemorySize, (int)smem);
    dim3 grid(N / BN, (M + 63) / 64);
    mma_gemm<NT, GELU, WSPLIT, WF32><<<grid, 256, smem>>>(
        Ah, Al, Wh, Wl, bias, C, Chi, Clo, M, N, K);
}

template<typename T>
static T* sym(T& s) { void* p; cudaGetSymbolAddress(&p, s); return (T*)p; }

extern "C" void kernel_launch(void* const* d_in, const int* in_sizes, int n_in,
                              void* d_out, int out_size)
{
    (void)in_sizes; (void)n_in; (void)out_size;
    const int*   eids   = (const int*)d_in[0];
    const int*   nids   = (const int*)d_in[1];
    const float* mask   = (const float*)d_in[2];
    const float* rel_emb= (const float*)d_in[3];
    const float* rp_b   = (const float*)d_in[5];
    const float* vbp    = (const float*)d_in[7];
    const float* obp    = (const float*)d_in[9];
    const float* n1g    = (const float*)d_in[10];
    const float* n1b    = (const float*)d_in[11];
    const float* n2g    = (const float*)d_in[12];
    const float* n2b    = (const float*)d_in[13];
    const float* b1     = (const float*)d_in[15];
    const float* b2     = (const float*)d_in[17];
    const float* tqb    = (const float*)d_in[20];
    const float* tkb    = (const float*)d_in[22];
    const float* tvb    = (const float*)d_in[24];
    const float* tob    = (const float*)d_in[26];
    const float* pb     = (const float*)d_in[28];
    float* out = (float*)d_out;

    // resolve symbol addresses
    float* ptable = (float*)0; cudaGetSymbolAddress((void**)&ptable, g_ptable);
    float* states = (float*)0; cudaGetSymbolAddress((void**)&states, g_states);
    float* tmp    = (float*)0; cudaGetSymbolAddress((void**)&tmp,    g_tmp);
    float* tmp2   = (float*)0; cudaGetSymbolAddress((void**)&tmp2,   g_tmp2);
    float* q      = (float*)0; cudaGetSymbolAddress((void**)&q,      g_q);
    float* k      = (float*)0; cudaGetSymbolAddress((void**)&k,      g_k);
    float* v      = (float*)0; cudaGetSymbolAddress((void**)&v,      g_v);

    __nv_bfloat16 *relh, *rell, *rpwh, *rpwl, *vwh, *vwl, *owh, *owl;
    __nv_bfloat16 *w1h, *w1l, *w2h, *w2l, *tqwh, *tqwl, *tkwh, *tkwl;
    __nv_bfloat16 *tvwh, *tvwl, *towh, *towl, *pwh, *pwl, *memqh, *memql;
    __nv_bfloat16 *aggh, *aggl, *sth, *stl, *tAh, *tAl, *hidh, *hidl;
    __nv_bfloat16 *memh, *meml, *m2h, *m2l;
    cudaGetSymbolAddress((void**)&relh, g_relh);   cudaGetSymbolAddress((void**)&rell, g_rell);
    cudaGetSymbolAddress((void**)&rpwh, g_rpwh);   cudaGetSymbolAddress((void**)&rpwl, g_rpwl);
    cudaGetSymbolAddress((void**)&vwh,  g_vwh);    cudaGetSymbolAddress((void**)&vwl,  g_vwl);
    cudaGetSymbolAddress((void**)&owh,  g_owh);    cudaGetSymbolAddress((void**)&owl,  g_owl);
    cudaGetSymbolAddress((void**)&w1h,  g_w1h);    cudaGetSymbolAddress((void**)&w1l,  g_w1l);
    cudaGetSymbolAddress((void**)&w2h,  g_w2h);    cudaGetSymbolAddress((void**)&w2l,  g_w2l);
    cudaGetSymbolAddress((void**)&tqwh, g_tqwh);   cudaGetSymbolAddress((void**)&tqwl, g_tqwl);
    cudaGetSymbolAddress((void**)&tkwh, g_tkwh);   cudaGetSymbolAddress((void**)&tkwl, g_tkwl);
    cudaGetSymbolAddress((void**)&tvwh, g_tvwh);   cudaGetSymbolAddress((void**)&tvwl, g_tvwl);
    cudaGetSymbolAddress((void**)&towh, g_towh);   cudaGetSymbolAddress((void**)&towl, g_towl);
    cudaGetSymbolAddress((void**)&pwh,  g_pwh);    cudaGetSymbolAddress((void**)&pwl,  g_pwl);
    cudaGetSymbolAddress((void**)&memqh,g_memqh);  cudaGetSymbolAddress((void**)&memql,g_memql);
    cudaGetSymbolAddress((void**)&aggh, g_aggh);   cudaGetSymbolAddress((void**)&aggl, g_aggl);
    cudaGetSymbolAddress((void**)&sth,  g_sth);    cudaGetSymbolAddress((void**)&stl,  g_stl);
    cudaGetSymbolAddress((void**)&tAh,  g_tAh);    cudaGetSymbolAddress((void**)&tAl,  g_tAl);
    cudaGetSymbolAddress((void**)&hidh, g_hidh);   cudaGetSymbolAddress((void**)&hidl, g_hidl);
    cudaGetSymbolAddress((void**)&memh, g_memh);   cudaGetSymbolAddress((void**)&meml, g_meml);
    cudaGetSymbolAddress((void**)&m2h,  g_m2h);    cudaGetSymbolAddress((void**)&m2l,  g_m2l);

    // 0) split all static GEMM operands to bf16 hi/lo
    {
        SJobs jb;
        const float* srcs[12] = { rel_emb, (const float*)d_in[4], (const float*)d_in[6],
                                  (const float*)d_in[8], (const float*)d_in[14],
                                  (const float*)d_in[16], (const float*)d_in[19],
                                  (const float*)d_in[21], (const float*)d_in[23],
                                  (const float*)d_in[25], (const float*)d_in[27],
                                  (const float*)d_in[18] };
        __nv_bfloat16* his[12] = { relh, rpwh, vwh, owh, w1h, w2h, tqwh, tkwh, tvwh, towh, pwh, memqh };
        __nv_bfloat16* los[12] = { rell, rpwl, vwl, owl, w1l, w2l, tqwl, tkwl, tvwl, towl, pwl, memql };
        const unsigned n4[12] = { Rsz*RDsz/4, Dsz*RDsz/4, Lsz*Dsz*Dsz/4, Lsz*Dsz*Dsz/4,
                                  Lsz*4*Dsz*Dsz/4, Lsz*4*Dsz*Dsz/4, Dsz*Dsz/4, Dsz*Dsz/4,
                                  Dsz*Dsz/4, Dsz*Dsz/4, HLLMsz*Dsz/4, Msz*Dsz/4 };
        unsigned cum = 0;
        for (int i = 0; i < 12; i++) {
            jb.src[i] = (const float4*)srcs[i];
            jb.hi[i]  = (uint2*)his[i];
            jb.lo[i]  = (uint2*)los[i];
            cum += n4[i];
            jb.end4[i] = cum;
        }
        jb.cnt = 12;
        jb.total4 = cum;
        split_multi<<<(cum + 255) / 256, 256>>>(jb);
    }

    // 1) project ALL relation embeddings once
    run_gemm<4,false,false,true>(relh, rell, rpwh, rpwl, rp_b, ptable, 0, 0, Rsz, Dsz, RDsz);
    row_norm_kernel<<<Rsz, 128>>>();

    // 2) per-edge cosine sims, top-8, aggregate (writes agg split + states fp32)
    sim_topk_agg<<<BE, 256>>>(eids, nids);

    // 3) relation-context layers
    for (int l = 0; l < Lsz; l++) {
        run_gemm<4,false,true,false>(aggh, aggl, vwh + (size_t)l*Dsz*Dsz, vwl + (size_t)l*Dsz*Dsz,
                                     vbp + l*Dsz, 0, tAh, tAl, BE, Dsz, Dsz);
        run_gemm<4,false,false,true>(tAh, tAl, owh + (size_t)l*Dsz*Dsz, owl + (size_t)l*Dsz*Dsz,
                                     obp + l*Dsz, tmp2, 0, 0, BE, Dsz, Dsz);
        add_ln<<<BE, 256>>>(states, tmp2, states, n1g + l*Dsz, n1b + l*Dsz, nullptr);
        run_gemm<8,true,true,false>(sth, stl, w1h + (size_t)l*4*Dsz*Dsz, w1l + (size_t)l*4*Dsz*Dsz,
                                    b1 + l*4*Dsz, 0, hidh, hidl, BE, 4*Dsz, Dsz);
        run_gemm<4,false,false,true>(hidh, hidl, w2h + (size_t)l*Dsz*4*Dsz, w2l + (size_t)l*Dsz*4*Dsz,
                                     b2 + l*Dsz, tmp, 0, 0, BE, Dsz, 4*Dsz);
        add_ln<<<BE, 256>>>(states, tmp, states, n2g + l*Dsz, n2b + l*Dsz, mask);
    }

    // 4) memory tokenizer
    run_gemm<4,false,false,true>(memqh, memql, tqwh, tqwl, tqb, q, 0, 0, Msz, Dsz, Dsz);
    run_gemm<4,false,false,true>(sth, stl, tkwh, tkwl, tkb, k, 0, 0, BE, Dsz, Dsz);
    run_gemm<4,false,false,true>(sth, stl, tvwh, tvwl, tvb, v, 0, 0, BE, Dsz, Dsz);
    mem_attn<<<Bsz*Msz, 256>>>(mask);
    run_gemm<4,false,true,false>(memh, meml, towh, towl, tob, 0, m2h, m2l, Bsz*Msz, Dsz, Dsz);
    zero_noedge<<<Bsz, 256>>>(mask);

    // 5) final projection to LLM hidden size
    run_gemm<8,false,false,true>(m2h, m2l, pwh, pwl, pb, out, 0, 0, Bsz*Msz, HLLMsz, Dsz);
}

// round 8
// speedup vs baseline: 3.2952x; 1.0367x over previous
#include <cuda_runtime.h>
#include <cuda_bf16.h>
#include <math.h>
#include <stdint.h>

// Problem constants
#define Bsz   8
#define Esz   256
#define Nsz   32
#define Dsz   512
#define RDsz  768
#define Rsz   2000
#define Lsz   2
#define Ksel  8
#define Msz   32
#define Hsz   8
#define DHsz  64
#define HLLMsz 4096
#define BE    (Bsz*Esz)   // 2048

// fp32 scratch
__device__ float g_ptable[Rsz*Dsz];
__device__ float g_norms[Rsz];
__device__ float g_states[BE*Dsz];
__device__ float g_tmp[BE*Dsz];
__device__ float g_tmp2[BE*Dsz];
__device__ float g_q[Msz*Dsz];
__device__ float g_k[BE*Dsz];
__device__ float g_v[BE*Dsz];

// bf16 hi/lo split scratch
__device__ __nv_bfloat16 g_relh[Rsz*RDsz],      g_rell[Rsz*RDsz];
__device__ __nv_bfloat16 g_rpwh[Dsz*RDsz],      g_rpwl[Dsz*RDsz];
__device__ __nv_bfloat16 g_vwh[Lsz*Dsz*Dsz],    g_vwl[Lsz*Dsz*Dsz];
__device__ __nv_bfloat16 g_owh[Lsz*Dsz*Dsz],    g_owl[Lsz*Dsz*Dsz];
__device__ __nv_bfloat16 g_w1h[Lsz*4*Dsz*Dsz],  g_w1l[Lsz*4*Dsz*Dsz];
__device__ __nv_bfloat16 g_w2h[Lsz*4*Dsz*Dsz],  g_w2l[Lsz*4*Dsz*Dsz];
__device__ __nv_bfloat16 g_tqwh[Dsz*Dsz],       g_tqwl[Dsz*Dsz];
__device__ __nv_bfloat16 g_tkwh[Dsz*Dsz],       g_tkwl[Dsz*Dsz];
__device__ __nv_bfloat16 g_tvwh[Dsz*Dsz],       g_tvwl[Dsz*Dsz];
__device__ __nv_bfloat16 g_towh[Dsz*Dsz],       g_towl[Dsz*Dsz];
__device__ __nv_bfloat16 g_pwh[HLLMsz*Dsz],     g_pwl[HLLMsz*Dsz];
__device__ __nv_bfloat16 g_memqh[Msz*Dsz],      g_memql[Msz*Dsz];
__device__ __nv_bfloat16 g_aggh[BE*Dsz],        g_aggl[BE*Dsz];
__device__ __nv_bfloat16 g_sth[BE*Dsz],         g_stl[BE*Dsz];
__device__ __nv_bfloat16 g_tAh[BE*Dsz],         g_tAl[BE*Dsz];
__device__ __nv_bfloat16 g_hidh[BE*4*Dsz],      g_hidl[BE*4*Dsz];
__device__ __nv_bfloat16 g_memh[Bsz*Msz*Dsz],   g_meml[Bsz*Msz*Dsz];
__device__ __nv_bfloat16 g_m2h[Bsz*Msz*Dsz],    g_m2l[Bsz*Msz*Dsz];

// ---------------------------------------------------------------------------
__device__ __forceinline__ uint32_t smem_u32(const void* p) {
    uint32_t a;
    asm("{ .reg .u64 t; cvta.to.shared.u64 t, %1; cvt.u32.u64 %0, t; }"
        : "=r"(a) : "l"(p));
    return a;
}

__device__ __forceinline__ void mma_bf16(float* c, const uint32_t* a, const uint32_t* b)
{
    asm volatile(
        "mma.sync.aligned.m16n8k16.row.col.f32.bf16.bf16.f32 "
        "{%0,%1,%2,%3}, {%4,%5,%6,%7}, {%8,%9}, {%0,%1,%2,%3};"
        : "+f"(c[0]), "+f"(c[1]), "+f"(c[2]), "+f"(c[3])
        : "r"(a[0]), "r"(a[1]), "r"(a[2]), "r"(a[3]), "r"(b[0]), "r"(b[1]));
}

__device__ __forceinline__ void ldm4(uint32_t* d, uint32_t addr)
{
    asm volatile("ldmatrix.sync.aligned.m8n8.x4.shared.b16 {%0,%1,%2,%3}, [%4];"
        : "=r"(d[0]), "=r"(d[1]), "=r"(d[2]), "=r"(d[3]) : "r"(addr));
}

__device__ __forceinline__ void split2(float x, float y, uint32_t& hi, uint32_t& lo)
{
    __nv_bfloat162 h = __floats2bfloat162_rn(x, y);
    float2 hf = __bfloat1622float2(h);
    __nv_bfloat162 l = __floats2bfloat162_rn(x - hf.x, y - hf.y);
    hi = *reinterpret_cast<uint32_t*>(&h);
    lo = *reinterpret_cast<uint32_t*>(&l);
}

__device__ __forceinline__ void split_scalar(float v, __nv_bfloat16* hp, __nv_bfloat16* lp)
{
    __nv_bfloat16 h = __float2bfloat16(v);
    *hp = h;
    *lp = __float2bfloat16(v - __bfloat162float(h));
}

#define CP_ASYNC16(dst, src) \
    asm volatile("cp.async.cg.shared.global [%0], [%1], 16;" :: "r"(dst), "l"(src))
#define CP_COMMIT() asm volatile("cp.async.commit_group;" ::: "memory")

// ---------------------------------------------------------------------------
// Batched fp32 -> (hi,lo) bf16 split for all GEMM operands.
// ---------------------------------------------------------------------------
struct SJobs {
    const float4* src[12];
    uint2* hi[12];
    uint2* lo[12];
    unsigned end4[12];
    int cnt;
    unsigned total4;
};

__global__ __launch_bounds__(256)
void split_multi(SJobs jb)
{
    unsigned idx = blockIdx.x * 256u + threadIdx.x;
    if (idx >= jb.total4) return;
    int t = 0;
#pragma unroll 1
    for (int i = 0; i < jb.cnt; i++)
        if (idx < jb.end4[i]) { t = i; break; }
    unsigned start = (t == 0) ? 0u : jb.end4[t - 1];
    unsigned li = idx - start;
    float4 v = jb.src[t][li];
    uint32_t h0, l0, h1, l1;
    split2(v.x, v.y, h0, l0);
    split2(v.z, v.w, h1, l1);
    jb.hi[t][li] = make_uint2(h0, h1);
    jb.lo[t][li] = make_uint2(l0, l1);
}

// ---------------------------------------------------------------------------
// bf16x3 emulated-fp32 GEMM on mma.sync.m16n8k16 + ldmatrix.x4 + cp.async.
// Pre-split bf16 (hi,lo) operands. C = A @ W^T + bias (opt exact GELU).
// 256 threads = 8 warps as 4(m) x 2(n). BM=MT*64, BN=NT*16, BK=32, 3 stages.
// ---------------------------------------------------------------------------
template<int MT, int NT, bool GELU, bool WSPLIT, bool WF32>
__global__ __launch_bounds__(256)
void mma_gemm(const __nv_bfloat16* __restrict__ Ah, const __nv_bfloat16* __restrict__ Al,
              const __nv_bfloat16* __restrict__ Wh, const __nv_bfloat16* __restrict__ Wl,
              const float* __restrict__ bias, float* __restrict__ C,
              __nv_bfloat16* __restrict__ Chi, __nv_bfloat16* __restrict__ Clo,
              int Mm, int Nn, int Kk)
{
    constexpr int BM    = MT * 64;
    constexpr int BN    = NT * 16;
    constexpr int ROWS  = BM + BN;
    constexpr int CHc   = ROWS * 8 / 256;   // 16B cp.async chunks per thread
    constexpr int BUF   = ROWS * 64;        // bytes per (stage-half) buffer
    constexpr int PAIRS = NT / 2;

    extern __shared__ char smraw[];
    const uint32_t sbase = smem_u32(smraw);

    const int tid  = threadIdx.x;
    const int lane = tid & 31;
    const int wid  = tid >> 5;
    const int m0 = blockIdx.y * BM;
    const int n0 = blockIdx.x * BN;
    const int mw = (wid >> 1) * (MT * 16);
    const int nw = (wid & 1) * (NT * 8);
    const int r  = lane >> 2;
    const int cq = lane & 3;

    float acc[MT][NT][4];
#pragma unroll
    for (int mt = 0; mt < MT; mt++)
#pragma unroll
        for (int j = 0; j < NT; j++)
#pragma unroll
            for (int t = 0; t < 4; t++) acc[mt][j][t] = 0.f;

    // staging: chunk idx over [hi: ROWS*4][lo: ROWS*4], 16B chunks
    const __nv_bfloat16* gp[CHc];
    bool val[CHc];
    uint32_t soff[CHc];
#pragma unroll
    for (int i = 0; i < CHc; i++) {
        int idx = i * 256 + tid;
        int b   = idx >= ROWS * 4;
        int rem = idx - b * ROWS * 4;
        int rr  = rem >> 2;
        int q   = rem & 3;
        soff[i] = (uint32_t)(b * BUF + rr * 64 + ((q ^ ((rr >> 1) & 3)) * 16));
        const __nv_bfloat16* src;
        int grow;
        if (rr < BM) { src = b ? Al : Ah; grow = m0 + rr; val[i] = grow < Mm; }
        else         { src = b ? Wl : Wh; grow = n0 + rr - BM; val[i] = true; }
        gp[i] = src + (size_t)grow * Kk + q * 8;
    }

    // ldmatrix lane addressing
    const int rrA0 = mw + ((lane >> 3) & 1) * 8 + (lane & 7);
    uint32_t arow[MT];
    int aswz[MT];
#pragma unroll
    for (int mt = 0; mt < MT; mt++) {
        int rr = rrA0 + mt * 16;
        arow[mt] = (uint32_t)(rr * 64);
        aswz[mt] = (rr >> 1) & 3;
    }
    const int akk = lane >> 4;
    uint32_t brow[PAIRS];
    int bswz[PAIRS];
    const int bkk = (lane >> 3) & 1;
#pragma unroll
    for (int p = 0; p < PAIRS; p++) {
        int rrB = BM + nw + (p * 2 + (lane >> 4)) * 8 + (lane & 7);
        brow[p] = (uint32_t)(rrB * 64);
        bswz[p] = (rrB >> 1) & 3;
    }

    const int nkt = Kk >> 5;            // BK = 32; all K here give nkt >= 16

    // prologue: stages 0 and 1
#pragma unroll
    for (int i = 0; i < CHc; i++)
        if (val[i]) CP_ASYNC16(sbase + soff[i], gp[i]);
    CP_COMMIT();
    {
        const uint32_t dst = sbase + (uint32_t)2 * BUF;
#pragma unroll
        for (int i = 0; i < CHc; i++)
            if (val[i]) CP_ASYNC16(dst + soff[i], gp[i] + 32);
    }
    CP_COMMIT();

#pragma unroll 1
    for (int kt = 0; kt < nkt; kt++) {
        asm volatile("cp.async.wait_group 1;" ::: "memory");
        __syncthreads();
        // issue stage kt+2 (overwrites stage (kt-1)%3 — all warps are past it)
        if (kt + 2 < nkt) {
            const int sn = (kt + 2) % 3;
            const uint32_t dst = sbase + (uint32_t)(sn * 2) * BUF;
            const size_t koff = (size_t)(kt + 2) * 32;
#pragma unroll
            for (int i = 0; i < CHc; i++)
                if (val[i]) CP_ASYNC16(dst + soff[i], gp[i] + koff);
        }
        CP_COMMIT();

        const int s = kt % 3;
        const uint32_t Hb = sbase + (uint32_t)(s * 2) * BUF;
        const uint32_t Lb = Hb + BUF;
#pragma unroll
        for (int ks = 0; ks < 2; ks++) {
            uint32_t ah[MT][4], al[MT][4];
#pragma unroll
            for (int mt = 0; mt < MT; mt++) {
                const uint32_t ak = (uint32_t)(((ks * 2 + akk) ^ aswz[mt]) * 16);
                ldm4(ah[mt], Hb + arow[mt] + ak);
                ldm4(al[mt], Lb + arow[mt] + ak);
            }
#pragma unroll
            for (int p = 0; p < PAIRS; p++) {
                uint32_t bh[4], bl[4];
                const uint32_t bk = (uint32_t)(((ks * 2 + bkk) ^ bswz[p]) * 16);
                ldm4(bh, Hb + brow[p] + bk);
                ldm4(bl, Lb + brow[p] + bk);
#pragma unroll
                for (int t = 0; t < 2; t++) {
                    const int j = p * 2 + t;
#pragma unroll
                    for (int mt = 0; mt < MT; mt++) {
                        mma_bf16(acc[mt][j], ah[mt], bh + 2 * t);
                        mma_bf16(acc[mt][j], al[mt], bh + 2 * t);
                        mma_bf16(acc[mt][j], ah[mt], bl + 2 * t);
                    }
                }
            }
        }
    }

    // epilogue
#pragma unroll
    for (int mt = 0; mt < MT; mt++) {
        const int row0 = m0 + mw + mt * 16 + r;
#pragma unroll
        for (int j = 0; j < NT; j++) {
            const int col = n0 + nw + j * 8 + cq * 2;
            const float b0v = __ldg(&bias[col]);
            const float b1v = __ldg(&bias[col + 1]);
            float v0 = acc[mt][j][0] + b0v;
            float v1 = acc[mt][j][1] + b1v;
            float v2 = acc[mt][j][2] + b0v;
            float v3 = acc[mt][j][3] + b1v;
            if (GELU) {
                v0 = 0.5f * v0 * (1.f + erff(v0 * 0.70710678118654752f));
                v1 = 0.5f * v1 * (1.f + erff(v1 * 0.70710678118654752f));
                v2 = 0.5f * v2 * (1.f + erff(v2 * 0.70710678118654752f));
                v3 = 0.5f * v3 * (1.f + erff(v3 * 0.70710678118654752f));
            }
            if (row0 < Mm) {
                const size_t o = (size_t)row0 * Nn + col;
                if (WF32) { C[o] = v0; C[o + 1] = v1; }
                if (WSPLIT) {
                    uint32_t h, l; split2(v0, v1, h, l);
                    *(uint32_t*)&Chi[o] = h; *(uint32_t*)&Clo[o] = l;
                }
            }
            if (row0 + 8 < Mm) {
                const size_t o = (size_t)(row0 + 8) * Nn + col;
                if (WF32) { C[o] = v2; C[o + 1] = v3; }
                if (WSPLIT) {
                    uint32_t h, l; split2(v2, v3, h, l);
                    *(uint32_t*)&Chi[o] = h; *(uint32_t*)&Clo[o] = l;
                }
            }
        }
    }
}

// ---------------------------------------------------------------------------
__device__ __forceinline__ float block_sum_256(float v, float* red)
{
    for (int o = 16; o; o >>= 1) v += __shfl_xor_sync(0xffffffffu, v, o);
    int w = threadIdx.x >> 5;
    if ((threadIdx.x & 31) == 0) red[w] = v;
    __syncthreads();
    float r = 0.f;
    if (threadIdx.x < 8) {
        r = red[threadIdx.x];
        for (int o = 4; o; o >>= 1) r += __shfl_xor_sync(0xffu, r, o);
        if (threadIdx.x == 0) red[0] = r;
    }
    __syncthreads();
    r = red[0];
    __syncthreads();
    return r;
}

__global__ __launch_bounds__(128)
void row_norm_kernel()
{
    int r = blockIdx.x;
    int tid = threadIdx.x;
    float4 v = ((const float4*)&g_ptable[(size_t)r * Dsz])[tid];
    float s = v.x*v.x + v.y*v.y + v.z*v.z + v.w*v.w;
    for (int o = 16; o; o >>= 1) s += __shfl_xor_sync(0xffffffffu, s, o);
    __shared__ float red[4];
    if ((tid & 31) == 0) red[tid >> 5] = s;
    __syncthreads();
    if (tid == 0)
        g_norms[r] = sqrtf(red[0] + red[1] + red[2] + red[3]);
}

__global__ __launch_bounds__(256)
void sim_topk_agg(const int* __restrict__ eids, const int* __restrict__ nids)
{
    int be = blockIdx.x;
    int tid = threadIdx.x;
    __shared__ float4 ev4[Dsz / 4];
    __shared__ float sims[Nsz];
    __shared__ int   selnid[Ksel];
    int eid = eids[be];
    if (tid < 128)
        ev4[tid] = ((const float4*)&g_ptable[(size_t)eid * Dsz])[tid];
    __syncthreads();
    float enorm = fmaxf(g_norms[eid], 1e-12f);
    int warp = tid >> 5, lane = tid & 31;
#pragma unroll
    for (int t = 0; t < 4; t++) {
        int n = warp * 4 + t;
        int nid = nids[be * Nsz + n];
        const float4* nv = (const float4*)&g_ptable[(size_t)nid * Dsz];
        float s = 0.f;
#pragma unroll
        for (int j = 0; j < 4; j++) {
            float4 a = nv[lane + 32 * j];
            float4 b = ev4[lane + 32 * j];
            s = fmaf(a.x, b.x, s); s = fmaf(a.y, b.y, s);
            s = fmaf(a.z, b.z, s); s = fmaf(a.w, b.w, s);
        }
        for (int o = 16; o; o >>= 1) s += __shfl_xor_sync(0xffffffffu, s, o);
        if (lane == 0)
            sims[n] = s / (enorm * fmaxf(g_norms[nid], 1e-12f));
    }
    __syncthreads();
    if (tid == 0) {
        unsigned used = 0;
        for (int j = 0; j < Ksel; j++) {
            float best = -3.402823466e38f; int bi = 0;
            for (int n = 0; n < Nsz; n++)
                if (!((used >> n) & 1u) && sims[n] > best) { best = sims[n]; bi = n; }
            used |= 1u << bi;
            selnid[j] = nids[be * Nsz + bi];
        }
    }
    __syncthreads();
    // aggregate: each thread owns one float2 slot
    float2 s2 = make_float2(0.f, 0.f);
#pragma unroll
    for (int j = 0; j < Ksel; j++) {
        float2 vq = ((const float2*)&g_ptable[(size_t)selnid[j] * Dsz])[tid];
        s2.x += vq.x; s2.y += vq.y;
    }
    s2.x *= 0.125f; s2.y *= 0.125f;
    const size_t o = (size_t)be * Dsz + tid * 2;
    uint32_t h, l;
    split2(s2.x, s2.y, h, l);
    *(uint32_t*)&g_aggh[o] = h;
    *(uint32_t*)&g_aggl[o] = l;
}

// states = LN(x + add) * mask; x optionally gathered via xidx from g_ptable
__global__ __launch_bounds__(256)
void add_ln(const float* __restrict__ x, const int* __restrict__ xidx,
            const float* __restrict__ add,
            float* __restrict__ out, const float* __restrict__ g,
            const float* __restrict__ b, const float* __restrict__ mask)
{
    int row = blockIdx.x;
    int tid = threadIdx.x;
    __shared__ float red[8];
    size_t base = (size_t)row * Dsz;
    const float* xr = xidx ? &g_ptable[(size_t)xidx[row] * Dsz] : &x[base];
    float v0 = xr[tid]       + add[base + tid];
    float v1 = xr[tid + 256] + add[base + tid + 256];
    float total = block_sum_256(v0 + v1, red);
    float mu = total * (1.f / Dsz);
    float d0 = v0 - mu, d1 = v1 - mu;
    float var = block_sum_256(d0*d0 + d1*d1, red) * (1.f / Dsz);
    float inv = rsqrtf(var + 1e-5f);
    float mk = mask ? mask[row] : 1.f;
    float o0 = (d0 * inv * g[tid]       + b[tid])       * mk;
    float o1 = (d1 * inv * g[tid + 256] + b[tid + 256]) * mk;
    out[base + tid]       = o0;
    out[base + tid + 256] = o1;
    split_scalar(o0, &g_sth[base + tid],       &g_stl[base + tid]);
    split_scalar(o1, &g_sth[base + tid + 256], &g_stl[base + tid + 256]);
}

__global__ __launch_bounds__(256)
void mem_attn(const float* __restrict__ mask)
{
    int b = blockIdx.x >> 5;
    int m = blockIdx.x & 31;
    int tid = threadIdx.x;
    __shared__ float qs[Dsz];
    __shared__ float sc[Hsz][Esz];
    qs[tid]       = g_q[m*Dsz + tid];
    qs[tid + 256] = g_q[m*Dsz + tid + 256];
    __syncthreads();
    {
        int e = tid;
        const float* kr = &g_k[((size_t)b*Esz + e)*Dsz];
        float mk = mask[b*Esz + e];
#pragma unroll
        for (int h = 0; h < Hsz; h++) {
            float s = 0.f;
#pragma unroll
            for (int d = 0; d < DHsz; d += 4) {
                float4 kq = *(const float4*)&kr[h*DHsz + d];
                float4 qq = *(const float4*)&qs[h*DHsz + d];
                s = fmaf(kq.x, qq.x, s); s = fmaf(kq.y, qq.y, s);
                s = fmaf(kq.z, qq.z, s); s = fmaf(kq.w, qq.w, s);
            }
            s *= 0.125f;
            sc[h][e] = (mk == 0.f) ? -3.402823466e38f : s;
        }
    }
    __syncthreads();
    {
        int w = tid >> 5, lane = tid & 31;
        float vals[8];
        float mx = -3.402823466e38f;
#pragma unroll
        for (int j = 0; j < 8; j++) { vals[j] = sc[w][lane + 32*j]; mx = fmaxf(mx, vals[j]); }
        for (int o = 16; o; o >>= 1) mx = fmaxf(mx, __shfl_xor_sync(0xffffffffu, mx, o));
        float sm = 0.f;
#pragma unroll
        for (int j = 0; j < 8; j++) { vals[j] = expf(vals[j] - mx); sm += vals[j]; }
        for (int o = 16; o; o >>= 1) sm += __shfl_xor_sync(0xffffffffu, sm, o);
        float inv = 1.f / sm;
#pragma unroll
        for (int j = 0; j < 8; j++) sc[w][lane + 32*j] = vals[j] * inv;
    }
    __syncthreads();
    float a0 = 0.f, a1 = 0.f;
    int od0 = tid, od1 = tid + 256;
    int h0 = od0 >> 6, h1 = od1 >> 6;
    for (int e = 0; e < Esz; e++) {
        const float* vr = &g_v[((size_t)b*Esz + e)*Dsz];
        a0 = fmaf(sc[h0][e], vr[od0], a0);
        a1 = fmaf(sc[h1][e], vr[od1], a1);
    }
    size_t ob = (size_t)blockIdx.x * Dsz;
    split_scalar(a0, &g_memh[ob + od0], &g_meml[ob + od0]);
    split_scalar(a1, &g_memh[ob + od1], &g_meml[ob + od1]);
}

__global__ __launch_bounds__(256)
void zero_noedge(const float* __restrict__ mask)
{
    int b = blockIdx.x;
    __shared__ float red[8];
    float total = block_sum_256(mask[b*Esz + threadIdx.x], red);
    if (total == 0.f) {
        uint32_t* h = (uint32_t*)&g_m2h[(size_t)b*Msz*Dsz];
        uint32_t* l = (uint32_t*)&g_m2l[(size_t)b*Msz*Dsz];
        for (int i = threadIdx.x; i < Msz*Dsz/2; i += 256) { h[i] = 0u; l[i] = 0u; }
    }
}

// ---------------------------------------------------------------------------
template<int MT, int NT, bool GELU, bool WSPLIT, bool WF32>
static void run_gemm(const __nv_bfloat16* Ah, const __nv_bfloat16* Al,
                     const __nv_bfloat16* Wh, const __nv_bfloat16* Wl,
                     const float* bias, float* C,
                     __nv_bfloat16* Chi, __nv_bfloat16* Clo,
                     int M, int N, int K)
{
    constexpr int BM = MT * 64;
    constexpr int BN = NT * 16;
    constexpr int ROWS = BM + BN;
    const size_t smem = (size_t)ROWS * 64 * 2 * 3;   // (hi+lo) * 3 stages
    cudaFuncSetAttribute(mma_gemm<MT, NT, GELU, WSPLIT, WF32>,
                         cudaFuncAttributeMaxDynamicSharedMemorySize, (int)smem);
    dim3 grid(N / BN, (M + BM - 1) / BM);
    mma_gemm<MT, NT, GELU, WSPLIT, WF32><<<grid, 256, smem>>>(
        Ah, Al, Wh, Wl, bias, C, Chi, Clo, M, N, K);
}

extern "C" void kernel_launch(void* const* d_in, const int* in_sizes, int n_in,
                              void* d_out, int out_size)
{
    (void)in_sizes; (void)n_in; (void)out_size;
    const int*   eids   = (const int*)d_in[0];
    const int*   nids   = (const int*)d_in[1];
    const float* mask   = (const float*)d_in[2];
    const float* rel_emb= (const float*)d_in[3];
    const float* rp_b   = (const float*)d_in[5];
    const float* vbp    = (const float*)d_in[7];
    const float* obp    = (const float*)d_in[9];
    const float* n1g    = (const float*)d_in[10];
    const float* n1b    = (const float*)d_in[11];
    const float* n2g    = (const float*)d_in[12];
    const float* n2b    = (const float*)d_in[13];
    const float* b1     = (const float*)d_in[15];
    const float* b2     = (const float*)d_in[17];
    const float* tqb    = (const float*)d_in[20];
    const float* tkb    = (const float*)d_in[22];
    const float* tvb    = (const float*)d_in[24];
    const float* tob    = (const float*)d_in[26];
    const float* pb     = (const float*)d_in[28];
    float* out = (float*)d_out;

    float *ptable, *states, *tmp, *tmp2, *q, *k, *v;
    cudaGetSymbolAddress((void**)&ptable, g_ptable);
    cudaGetSymbolAddress((void**)&states, g_states);
    cudaGetSymbolAddress((void**)&tmp,    g_tmp);
    cudaGetSymbolAddress((void**)&tmp2,   g_tmp2);
    cudaGetSymbolAddress((void**)&q,      g_q);
    cudaGetSymbolAddress((void**)&k,      g_k);
    cudaGetSymbolAddress((void**)&v,      g_v);

    __nv_bfloat16 *relh, *rell, *rpwh, *rpwl, *vwh, *vwl, *owh, *owl;
    __nv_bfloat16 *w1h, *w1l, *w2h, *w2l, *tqwh, *tqwl, *tkwh, *tkwl;
    __nv_bfloat16 *tvwh, *tvwl, *towh, *towl, *pwh, *pwl, *memqh, *memql;
    __nv_bfloat16 *aggh, *aggl, *sth, *stl, *tAh, *tAl, *hidh, *hidl;
    __nv_bfloat16 *memh, *meml, *m2h, *m2l;
    cudaGetSymbolAddress((void**)&relh, g_relh);   cudaGetSymbolAddress((void**)&rell, g_rell);
    cudaGetSymbolAddress((void**)&rpwh, g_rpwh);   cudaGetSymbolAddress((void**)&rpwl, g_rpwl);
    cudaGetSymbolAddress((void**)&vwh,  g_vwh);    cudaGetSymbolAddress((void**)&vwl,  g_vwl);
    cudaGetSymbolAddress((void**)&owh,  g_owh);    cudaGetSymbolAddress((void**)&owl,  g_owl);
    cudaGetSymbolAddress((void**)&w1h,  g_w1h);    cudaGetSymbolAddress((void**)&w1l,  g_w1l);
    cudaGetSymbolAddress((void**)&w2h,  g_w2h);    cudaGetSymbolAddress((void**)&w2l,  g_w2l);
    cudaGetSymbolAddress((void**)&tqwh, g_tqwh);   cudaGetSymbolAddress((void**)&tqwl, g_tqwl);
    cudaGetSymbolAddress((void**)&tkwh, g_tkwh);   cudaGetSymbolAddress((void**)&tkwl, g_tkwl);
    cudaGetSymbolAddress((void**)&tvwh, g_tvwh);   cudaGetSymbolAddress((void**)&tvwl, g_tvwl);
    cudaGetSymbolAddress((void**)&towh, g_towh);   cudaGetSymbolAddress((void**)&towl, g_towl);
    cudaGetSymbolAddress((void**)&pwh,  g_pwh);    cudaGetSymbolAddress((void**)&pwl,  g_pwl);
    cudaGetSymbolAddress((void**)&memqh,g_memqh);  cudaGetSymbolAddress((void**)&memql,g_memql);
    cudaGetSymbolAddress((void**)&aggh, g_aggh);   cudaGetSymbolAddress((void**)&aggl, g_aggl);
    cudaGetSymbolAddress((void**)&sth,  g_sth);    cudaGetSymbolAddress((void**)&stl,  g_stl);
    cudaGetSymbolAddress((void**)&tAh,  g_tAh);    cudaGetSymbolAddress((void**)&tAl,  g_tAl);
    cudaGetSymbolAddress((void**)&hidh, g_hidh);   cudaGetSymbolAddress((void**)&hidl, g_hidl);
    cudaGetSymbolAddress((void**)&memh, g_memh);   cudaGetSymbolAddress((void**)&meml, g_meml);
    cudaGetSymbolAddress((void**)&m2h,  g_m2h);    cudaGetSymbolAddress((void**)&m2l,  g_m2l);

    // 0) split all static GEMM operands to bf16 hi/lo
    {
        SJobs jb;
        const float* srcs[12] = { rel_emb, (const float*)d_in[4], (const float*)d_in[6],
                                  (const float*)d_in[8], (const float*)d_in[14],
                                  (const float*)d_in[16], (const float*)d_in[19],
                                  (const float*)d_in[21], (const float*)d_in[23],
                                  (const float*)d_in[25], (const float*)d_in[27],
                                  (const float*)d_in[18] };
        __nv_bfloat16* his[12] = { relh, rpwh, vwh, owh, w1h, w2h, tqwh, tkwh, tvwh, towh, pwh, memqh };
        __nv_bfloat16* los[12] = { rell, rpwl, vwl, owl, w1l, w2l, tqwl, tkwl, tvwl, towl, pwl, memql };
        const unsigned n4[12] = { Rsz*RDsz/4, Dsz*RDsz/4, Lsz*Dsz*Dsz/4, Lsz*Dsz*Dsz/4,
                                  Lsz*4*Dsz*Dsz/4, Lsz*4*Dsz*Dsz/4, Dsz*Dsz/4, Dsz*Dsz/4,
                                  Dsz*Dsz/4, Dsz*Dsz/4, HLLMsz*Dsz/4, Msz*Dsz/4 };
        unsigned cum = 0;
        for (int i = 0; i < 12; i++) {
            jb.src[i] = (const float4*)srcs[i];
            jb.hi[i]  = (uint2*)his[i];
            jb.lo[i]  = (uint2*)los[i];
            cum += n4[i];
            jb.end4[i] = cum;
        }
        jb.cnt = 12;
        jb.total4 = cum;
        split_multi<<<(cum + 255) / 256, 256>>>(jb);
    }

    // 1) project ALL relation embeddings once
    run_gemm<2,4,false,false,true>(relh, rell, rpwh, rpwl, rp_b, ptable, 0, 0, Rsz, Dsz, RDsz);
    row_norm_kernel<<<Rsz, 128>>>();

    // 2) per-edge cosine sims, top-8, aggregate
    sim_topk_agg<<<BE, 256>>>(eids, nids);

    // 3) relation-context layers
    for (int l = 0; l < Lsz; l++) {
        run_gemm<2,4,false,true,false>(aggh, aggl, vwh + (size_t)l*Dsz*Dsz, vwl + (size_t)l*Dsz*Dsz,
                                       vbp + l*Dsz, 0, tAh, tAl, BE, Dsz, Dsz);
        run_gemm<2,4,false,false,true>(tAh, tAl, owh + (size_t)l*Dsz*Dsz, owl + (size_t)l*Dsz*Dsz,
                                       obp + l*Dsz, tmp2, 0, 0, BE, Dsz, Dsz);
        add_ln<<<BE, 256>>>(states, (l == 0) ? eids : nullptr, tmp2, states,
                            n1g + l*Dsz, n1b + l*Dsz, nullptr);
        run_gemm<2,4,true,true,false>(sth, stl, w1h + (size_t)l*4*Dsz*Dsz, w1l + (size_t)l*4*Dsz*Dsz,
                                      b1 + l*4*Dsz, 0, hidh, hidl, BE, 4*Dsz, Dsz);
        run_gemm<2,4,false,false,true>(hidh, hidl, w2h + (size_t)l*Dsz*4*Dsz, w2l + (size_t)l*Dsz*4*Dsz,
                                       b2 + l*Dsz, tmp, 0, 0, BE, Dsz, 4*Dsz);
        add_ln<<<BE, 256>>>(states, nullptr, tmp, states,
                            n2g + l*Dsz, n2b + l*Dsz, mask);
    }

    // 4) memory tokenizer
    run_gemm<1,4,false,false,true>(memqh, memql, tqwh, tqwl, tqb, q, 0, 0, Msz, Dsz, Dsz);
    run_gemm<2,4,false,false,true>(sth, stl, tkwh, tkwl, tkb, k, 0, 0, BE, Dsz, Dsz);
    run_gemm<2,4,false,false,true>(sth, stl, tvwh, tvwl, tvb, v, 0, 0, BE, Dsz, Dsz);
    mem_attn<<<Bsz*Msz, 256>>>(mask);
    run_gemm<1,4,false,true,false>(memh, meml, towh, towl, tob, 0, m2h, m2l, Bsz*Msz, Dsz, Dsz);
    zero_noedge<<<Bsz, 256>>>(mask);

    // 5) final projection to LLM hidden size
    run_gemm<2,4,false,false,true>(m2h, m2l, pwh, pwl, pb, out, 0, 0, Bsz*Msz, HLLMsz, Dsz);
}